// round 8
// baseline (speedup 1.0000x reference)
#include <cuda_runtime.h>
#include <cuda_fp16.h>
#include <math.h>
#include <stdint.h>

#define FULLMASK 0xffffffffu
#define NCLS 10
#define MAXM 131072
#define MAXN 2048
#define NSPLIT 9
#define HB 256

// store z * log2(e) so ex2(-sqrt(sq')) = exp(-dist); norms * log2(e)^2
#define ZSCL 1.4426950408889634f
#define NSCL 2.081368981144074f

// ---------------- scratch (static device globals; no allocation) ------------
__device__ __half g_zc_h[MAXM * 128];
__device__ float  g_cn[MAXM];
__device__ __half g_z_h[MAXN * 128];
__device__ float  g_zn2[MAXN];
__device__ int    g_destMap[MAXM];
__device__ int    g_hist[(MAXM / HB) * NCLS];
__device__ int    g_classStart[NCLS + 1];
__device__ float  g_part[NSPLIT * MAXN * NCLS];

// ---------------- PTX helpers (baseline sm_80+ only) -------------------------
__device__ __forceinline__ uint32_t smem_u32(const void* p) {
    uint32_t a;
    asm("{ .reg .u64 t; cvta.to.shared.u64 t, %1; cvt.u32.u64 %0, t; }" : "=r"(a) : "l"(p));
    return a;
}

#define CP16(saddr, gptr) \
    asm volatile("cp.async.cg.shared.global [%0], [%1], 16;" :: "r"(saddr), "l"(gptr))
#define CP_COMMIT() asm volatile("cp.async.commit_group;" ::: "memory")
#define CP_WAIT(n)  asm volatile("cp.async.wait_group %0;" :: "n"(n) : "memory")

#define LDSM4(r, addr) \
    asm volatile("ldmatrix.sync.aligned.m8n8.x4.shared.b16 {%0,%1,%2,%3}, [%4];" \
        : "=r"((r)[0]), "=r"((r)[1]), "=r"((r)[2]), "=r"((r)[3]) : "r"(addr))

#define MMA_F16(d, a, b0v, b1v) \
    asm volatile("mma.sync.aligned.m16n8k16.row.col.f32.f16.f16.f32 " \
        "{%0,%1,%2,%3},{%4,%5,%6,%7},{%8,%9},{%0,%1,%2,%3};" \
        : "+f"((d)[0]), "+f"((d)[1]), "+f"((d)[2]), "+f"((d)[3]) \
        : "r"((a)[0]), "r"((a)[1]), "r"((a)[2]), "r"((a)[3]), "r"(b0v), "r"(b1v))

// ---------------- counting sort by class (256-thread blocks) -----------------
__global__ __launch_bounds__(HB)
void hist_k(const int* __restrict__ y, int M, int* __restrict__ hist) {
    __shared__ int wc[HB / 32][NCLS];
    int tid = threadIdx.x, w = tid >> 5;
    int i = blockIdx.x * HB + tid;
    int c = (i < M) ? y[i] : -1;
#pragma unroll
    for (int cls = 0; cls < NCLS; ++cls) {
        unsigned b = __ballot_sync(FULLMASK, c == cls);
        if ((tid & 31) == 0) wc[w][cls] = __popc(b);
    }
    __syncthreads();
    if (tid < NCLS) {
        int s = 0;
#pragma unroll
        for (int ww = 0; ww < HB / 32; ++ww) s += wc[ww][tid];
        hist[blockIdx.x * NCLS + tid] = s;
    }
}

__global__ void scan_k(int* hist, int NB, int* classStart) {
    __shared__ int tot[NCLS];
    int c = threadIdx.x;
    if (c < NCLS) {
        int run = 0;
        for (int b = 0; b < NB; ++b) {
            int t = hist[b * NCLS + c];
            hist[b * NCLS + c] = run;
            run += t;
        }
        tot[c] = run;
    }
    __syncthreads();
    if (threadIdx.x == 0) {
        int a = 0;
        for (int i = 0; i < NCLS; ++i) { classStart[i] = a; a += tot[i]; }
        classStart[NCLS] = a;
    }
}

__global__ __launch_bounds__(HB)
void scatter_k(const int* __restrict__ y, int M,
               const int* __restrict__ hist,
               const int* __restrict__ classStart,
               int* __restrict__ dest) {
    __shared__ int wc[HB / 32][NCLS];
    int tid = threadIdx.x, w = tid >> 5, lane = tid & 31;
    int i = blockIdx.x * HB + tid;
    int c = (i < M) ? y[i] : -1;
    unsigned mymask = 0;
#pragma unroll
    for (int cls = 0; cls < NCLS; ++cls) {
        unsigned b = __ballot_sync(FULLMASK, c == cls);
        if (lane == 0) wc[w][cls] = __popc(b);
        if (c == cls) mymask = b;
    }
    __syncthreads();
    if (tid < NCLS) {
        int run = 0;
#pragma unroll
        for (int ww = 0; ww < HB / 32; ++ww) {
            int t = wc[ww][tid];
            wc[ww][tid] = run;
            run += t;
        }
    }
    __syncthreads();
    if (i < M) {
        int rank = __popc(mymask & ((1u << lane) - 1u));
        dest[i] = classStart[c] + hist[blockIdx.x * NCLS + c] + wc[w][c] + rank;
    }
}

// ---------------- encoder: out[dest] = X[src]@W^T + b -> fp16*ZSCL + norms ---
__global__ __launch_bounds__(256, 2)
void encode_k(const float* __restrict__ X, int n, const int* __restrict__ destMap,
              const float* __restrict__ W, const float* __restrict__ bias,
              __half* __restrict__ outH, float* __restrict__ outN) {
    extern __shared__ char smc[];
    float* sm = (float*)smc;
    float* ws = sm;                       // [128][132]
    float* xs = sm + 128 * 132;           // [32][132]
    int*   dests = (int*)(sm + 128 * 132 + 32 * 132);

    int tid = threadIdx.x;
    int base = blockIdx.x * 32;

    for (int t = tid; t < 128 * 32; t += 256) {
        int row = t >> 5, q = t & 31;
        float4 v = ((const float4*)W)[row * 32 + q];
        *(float4*)&ws[row * 132 + q * 4] = v;
    }
    for (int t = tid; t < 32 * 32; t += 256) {
        int row = t >> 5, q = t & 31;
        float4 v = make_float4(0.f, 0.f, 0.f, 0.f);
        if (base + row < n) v = ((const float4*)X)[(size_t)(base + row) * 32 + q];
        *(float4*)&xs[row * 132 + q * 4] = v;
    }
    if (tid < 32)
        dests[tid] = (base + tid < n) ? (destMap ? destMap[base + tid] : base + tid) : -1;
    __syncthreads();

    int cgrp = tid & 31, rgrp = tid >> 5;
    float acc[4][4];
#pragma unroll
    for (int i = 0; i < 4; ++i)
#pragma unroll
        for (int j = 0; j < 4; ++j) acc[i][j] = 0.f;

#pragma unroll 4
    for (int k = 0; k < 128; k += 4) {
        float4 a[4], w4[4];
#pragma unroll
        for (int i = 0; i < 4; ++i) a[i] = *(const float4*)&xs[(rgrp * 4 + i) * 132 + k];
#pragma unroll
        for (int j = 0; j < 4; ++j) w4[j] = *(const float4*)&ws[(cgrp + 32 * j) * 132 + k];
#pragma unroll
        for (int i = 0; i < 4; ++i)
#pragma unroll
            for (int j = 0; j < 4; ++j) {
                acc[i][j] = fmaf(a[i].x, w4[j].x, acc[i][j]);
                acc[i][j] = fmaf(a[i].y, w4[j].y, acc[i][j]);
                acc[i][j] = fmaf(a[i].z, w4[j].z, acc[i][j]);
                acc[i][j] = fmaf(a[i].w, w4[j].w, acc[i][j]);
            }
    }

    float nrm[4] = {0.f, 0.f, 0.f, 0.f};
#pragma unroll
    for (int j = 0; j < 4; ++j) {
        int dim = cgrp + 32 * j;
        float bb = bias[dim];
#pragma unroll
        for (int i = 0; i < 4; ++i) {
            float v = acc[i][j] + bb;
            acc[i][j] = v;
            nrm[i] = fmaf(v, v, nrm[i]);
        }
    }
#pragma unroll
    for (int i = 0; i < 4; ++i) {
        int d = dests[rgrp * 4 + i];
        if (d >= 0) {
#pragma unroll
            for (int j = 0; j < 4; ++j)
                outH[(size_t)d * 128 + cgrp + 32 * j] = __float2half_rn(acc[i][j] * ZSCL);
        }
        float s = nrm[i];
#pragma unroll
        for (int off = 16; off > 0; off >>= 1) s += __shfl_xor_sync(FULLMASK, s, off);
        if (cgrp == 0 && d >= 0) outN[d] = s * NSCL;
    }
}

// ---------------- main: pipelined fp16 HMMA + interleaved MUFU epilogue ------
#define SM_ZH    0
#define SM_B     32768     // 2 stages x 32768
#define SM_CN    98304     // 2 x 512
#define SM_SACC  99328     // 128*10 floats
#define SM_TOTAL 104448

// async-copy one 128x128 fp16 tile (32KB) into swizzled smem; 512 threads
__device__ __forceinline__ void issue_tile(uint32_t sbase, const uint4* __restrict__ g,
                                           int tid) {
#pragma unroll
    for (int t = 0; t < 4; ++t) {
        int idx = tid + t * 512;            // 0..2047, = row*16 + chunk
        int row = idx >> 4, c = idx & 15;
        uint32_t saddr = sbase + row * 256 + ((c ^ (row & 7)) << 4);
        CP16(saddr, g + idx);
    }
}

// class-segmented column sums of a processed 32x32 slice into smem sacc
#define CLASS_SUM(ACC, WB) do {                                                  \
    int c0 = 0;                                                                  \
    while (c0 < NCLS - 1 && cs[c0 + 1] <= (WB)) ++c0;                            \
    int c1 = c0;                                                                 \
    while (c1 < NCLS - 1 && cs[c1 + 1] < (WB) + 32) ++c1;                        \
    if (c0 == c1) {                                                              \
        _Pragma("unroll")                                                        \
        for (int mi = 0; mi < 2; ++mi)                                           \
            _Pragma("unroll")                                                    \
            for (int h = 0; h < 2; ++h) {                                        \
                float s = 0.f;                                                   \
                _Pragma("unroll")                                                \
                for (int ni = 0; ni < 4; ++ni)                                   \
                    _Pragma("unroll")                                            \
                    for (int j = 0; j < 2; ++j) s += (ACC)[mi][ni][h * 2 + j];   \
                s += __shfl_xor_sync(FULLMASK, s, 1);                            \
                s += __shfl_xor_sync(FULLMASK, s, 2);                            \
                if ((lane & 3) == 0) {                                           \
                    int r = warpM * 32 + mi * 16 + (lane >> 2) + h * 8;          \
                    atomicAdd((float*)(sm + SM_SACC) + r * NCLS + c0, s);        \
                }                                                                \
            }                                                                    \
    } else {                                                                     \
        for (int c = c0; c <= c1; ++c) {                                         \
            int lo = max(cs[c] - (WB), 0), hi = min(cs[c + 1] - (WB), 32);       \
            _Pragma("unroll")                                                    \
            for (int mi = 0; mi < 2; ++mi)                                       \
                _Pragma("unroll")                                                \
                for (int h = 0; h < 2; ++h) {                                    \
                    float s = 0.f;                                               \
                    _Pragma("unroll")                                            \
                    for (int ni = 0; ni < 4; ++ni)                               \
                        _Pragma("unroll")                                        \
                        for (int j = 0; j < 2; ++j) {                            \
                            int nl = ni * 8 + q2 + j;                            \
                            s += (nl >= lo && nl < hi) ? (ACC)[mi][ni][h*2+j] : 0.f; \
                        }                                                        \
                    s += __shfl_xor_sync(FULLMASK, s, 1);                        \
                    s += __shfl_xor_sync(FULLMASK, s, 2);                        \
                    if ((lane & 3) == 0) {                                       \
                        int r = warpM * 32 + mi * 16 + (lane >> 2) + h * 8;      \
                        atomicAdd((float*)(sm + SM_SACC) + r * NCLS + c, s);     \
                    }                                                            \
                }                                                                \
        }                                                                        \
    }                                                                            \
} while (0)

__global__ __launch_bounds__(512, 1)
void nca_mma_k(const __half* __restrict__ zh_g, const float* __restrict__ zn2,
               const __half* __restrict__ ch_g, const float* __restrict__ cn_g,
               const int* __restrict__ classStart,
               float* __restrict__ part, int M, int N) {
    extern __shared__ char smc[];
    char* sm = smc;
    const uint32_t sb = smem_u32(sm);
    const int tid = threadIdx.x;
    const int w = tid >> 5, lane = tid & 31;
    const int warpM = w & 3, warpN = w >> 2;   // 4 x 4 warp grid; 32 x 32 per warp
    const int q2 = (lane & 3) * 2;
    const int tile = blockIdx.x, split = blockIdx.y;
    const int chunksTotal = M >> 7;
    const int cpb = (chunksTotal + NSPLIT - 1) / NSPLIT;
    const int cLo = split * cpb;
    const int cHi = min(cLo + cpb, chunksTotal);
    const int nch = cHi - cLo;

    for (int i = tid; i < 128 * NCLS; i += 512) ((float*)(sm + SM_SACC))[i] = 0.f;

    int cs[NCLS + 1];
#pragma unroll
    for (int k = 0; k <= NCLS; ++k) cs[k] = classStart[k];

    float znr[2][2];
#pragma unroll
    for (int mi = 0; mi < 2; ++mi) {
        int r = tile * 128 + warpM * 32 + mi * 16 + (lane >> 2);
        znr[mi][0] = zn2[r];
        znr[mi][1] = zn2[r + 8];
    }

    // prologue
    issue_tile(sb + SM_ZH, (const uint4*)zh_g + (size_t)tile * 2048, tid);
    issue_tile(sb + SM_B, (const uint4*)ch_g + (size_t)cLo * 2048, tid);
    if (tid < 32) CP16(sb + SM_CN + tid * 16, (const float*)cn_g + (size_t)cLo * 128 + tid * 4);
    CP_COMMIT();
    if (nch > 1) {
        issue_tile(sb + SM_B + 32768, (const uint4*)ch_g + (size_t)(cLo + 1) * 2048, tid);
        if (tid < 32) CP16(sb + SM_CN + 512 + tid * 16,
                           (const float*)cn_g + (size_t)(cLo + 1) * 128 + tid * 4);
    }
    CP_COMMIT();

    // ldmatrix address precompute
    uint32_t aoff[2], asw[2];
#pragma unroll
    for (int mi = 0; mi < 2; ++mi) {
        int row = warpM * 32 + mi * 16 + (lane & 15);
        aoff[mi] = row * 256;
        asw[mi] = row & 7;
    }
    const uint32_t achb = lane >> 4;
    uint32_t boff[2], bsw[2];
#pragma unroll
    for (int g = 0; g < 2; ++g) {
        int row = warpN * 32 + g * 16 + (lane & 7) + ((lane >> 4) << 3);
        boff[g] = row * 256;
        bsw[g] = row & 7;
    }
    const uint32_t bchb = (lane >> 3) & 1;

    // pipelined state: accP = previous chunk's dots (then exp), cnvP its norms
    float accP[2][4][4], cnvP[4][2];
#pragma unroll
    for (int mi = 0; mi < 2; ++mi)
#pragma unroll
        for (int ni = 0; ni < 4; ++ni)
#pragma unroll
            for (int k = 0; k < 4; ++k) accP[mi][ni][k] = 0.f;
#pragma unroll
    for (int ni = 0; ni < 4; ++ni) { cnvP[ni][0] = 0.f; cnvP[ni][1] = 0.f; }
    int wbP = 0;

    for (int i = 0; i < nch; ++i) {
        CP_WAIT(1);
        __syncthreads();

        const int cb = i & 1;
        const uint32_t bbase = sb + SM_B + cb * 32768;
        const uint32_t abase = sb + SM_ZH;

        float accC[2][4][4];
#pragma unroll
        for (int mi = 0; mi < 2; ++mi)
#pragma unroll
            for (int ni = 0; ni < 4; ++ni)
#pragma unroll
                for (int k = 0; k < 4; ++k) accC[mi][ni][k] = 0.f;

#pragma unroll
        for (int k8 = 0; k8 < 8; ++k8) {
            uint32_t af[2][4], bf[2][4];
            uint32_t ca = 2 * k8 + achb, cbk = 2 * k8 + bchb;
#pragma unroll
            for (int mi = 0; mi < 2; ++mi)
                LDSM4(af[mi], abase + aoff[mi] + ((ca ^ asw[mi]) << 4));
#pragma unroll
            for (int g = 0; g < 2; ++g)
                LDSM4(bf[g], bbase + boff[g] + ((cbk ^ bsw[g]) << 4));
#pragma unroll
            for (int mi = 0; mi < 2; ++mi)
#pragma unroll
                for (int ni = 0; ni < 4; ++ni) {
                    int g = ni >> 1, p = (ni & 1) * 2;
                    MMA_F16(accC[mi][ni], af[mi], bf[g][p], bf[g][p + 1]);
                }
            // interleaved MUFU epilogue of previous chunk: 4 elements per step
#pragma unroll
            for (int t = 0; t < 4; ++t) {
                int e = k8 * 4 + t;
                int mi = e >> 4, ni = (e >> 2) & 3, kk = e & 3;
                float base = znr[mi][kk >> 1] + cnvP[ni][kk & 1];
                float sq = fmaf(-2.f, accP[mi][ni][kk], base);
                float dd;
                asm("sqrt.approx.f32 %0, %1;" : "=f"(dd) : "f"(sq));
                float nd = -dd;
                asm("ex2.approx.f32 %0, %1;" : "=f"(accP[mi][ni][kk]) : "f"(nd));
            }
        }

        // current chunk's candidate norms (read before the stage is freed)
        float cnv[4][2];
#pragma unroll
        for (int ni = 0; ni < 4; ++ni) {
            cnv[ni][0] = *(const float*)(sm + SM_CN + cb * 512 + (warpN * 32 + ni * 8 + q2) * 4);
            cnv[ni][1] = *(const float*)(sm + SM_CN + cb * 512 + (warpN * 32 + ni * 8 + q2 + 1) * 4);
        }

        __syncthreads();

        // prefetch chunk i+2 into freed stage; DMA overlaps the class sums
        if (i + 2 < nch) {
            issue_tile(sb + SM_B + cb * 32768,
                       (const uint4*)ch_g + (size_t)(cLo + i + 2) * 2048, tid);
            if (tid < 32) CP16(sb + SM_CN + cb * 512 + tid * 16,
                               (const float*)cn_g + (size_t)(cLo + i + 2) * 128 + tid * 4);
        }
        CP_COMMIT();

        // class sums of previous chunk (accP now holds exp values)
        if (i > 0) { CLASS_SUM(accP, wbP); }

        // rotate: current becomes previous
#pragma unroll
        for (int mi = 0; mi < 2; ++mi)
#pragma unroll
            for (int ni = 0; ni < 4; ++ni)
#pragma unroll
                for (int k = 0; k < 4; ++k) accP[mi][ni][k] = accC[mi][ni][k];
#pragma unroll
        for (int ni = 0; ni < 4; ++ni) { cnvP[ni][0] = cnv[ni][0]; cnvP[ni][1] = cnv[ni][1]; }
        wbP = (cLo + i) * 128 + warpN * 32;
    }

    // drain: epilogue + class sums of the final chunk
#pragma unroll
    for (int mi = 0; mi < 2; ++mi)
#pragma unroll
        for (int ni = 0; ni < 4; ++ni)
#pragma unroll
            for (int kk = 0; kk < 4; ++kk) {
                float base = znr[mi][kk >> 1] + cnvP[ni][kk & 1];
                float sq = fmaf(-2.f, accP[mi][ni][kk], base);
                float dd;
                asm("sqrt.approx.f32 %0, %1;" : "=f"(dd) : "f"(sq));
                float nd = -dd;
                asm("ex2.approx.f32 %0, %1;" : "=f"(accP[mi][ni][kk]) : "f"(nd));
            }
    CLASS_SUM(accP, wbP);

    __syncthreads();
    if (tid < 128) {
        int qg = tile * 128 + tid;
#pragma unroll
        for (int c = 0; c < NCLS; ++c)
            part[((size_t)split * N + qg) * NCLS + c] =
                ((float*)(sm + SM_SACC))[tid * NCLS + c];
    }
}

// ---------------- finalize: combine splits, normalize, log ------------------
__global__ void finalize_k(const float* __restrict__ part, float* __restrict__ out, int N) {
    int n = blockIdx.x * blockDim.x + threadIdx.x;
    if (n >= N) return;
    float t[NCLS];
#pragma unroll
    for (int c = 0; c < NCLS; ++c) t[c] = 0.f;
    for (int s = 0; s < NSPLIT; ++s)
#pragma unroll
        for (int c = 0; c < NCLS; ++c) t[c] += part[((size_t)s * N + n) * NCLS + c];
    float tot = 0.f;
#pragma unroll
    for (int c = 0; c < NCLS; ++c) tot += t[c];
    float inv = 1.f / tot;
#pragma unroll
    for (int c = 0; c < NCLS; ++c) out[n * NCLS + c] = logf(fmaf(t[c], inv, 1e-7f));
}

// ---------------- launch ----------------------------------------------------
extern "C" void kernel_launch(void* const* d_in, const int* in_sizes, int n_in,
                              void* d_out, int out_size) {
    const float* x  = (const float*)d_in[0];
    const float* cx = (const float*)d_in[1];
    const int*   cy = (const int*)d_in[2];
    const float* W  = (const float*)d_in[3];
    const float* b  = (const float*)d_in[4];
    int N = in_sizes[0] / 128;
    int M = in_sizes[2];
    float* out = (float*)d_out;

    void *p_ch, *p_cn, *p_zh, *p_zn2, *p_dest, *p_hist, *p_cs, *p_part;
    cudaGetSymbolAddress(&p_ch, g_zc_h);
    cudaGetSymbolAddress(&p_cn, g_cn);
    cudaGetSymbolAddress(&p_zh, g_z_h);
    cudaGetSymbolAddress(&p_zn2, g_zn2);
    cudaGetSymbolAddress(&p_dest, g_destMap);
    cudaGetSymbolAddress(&p_hist, g_hist);
    cudaGetSymbolAddress(&p_cs, g_classStart);
    cudaGetSymbolAddress(&p_part, g_part);

    int NB = (M + HB - 1) / HB;
    hist_k<<<NB, HB>>>(cy, M, (int*)p_hist);
    scan_k<<<1, 32>>>((int*)p_hist, NB, (int*)p_cs);
    scatter_k<<<NB, HB>>>(cy, M, (const int*)p_hist, (const int*)p_cs, (int*)p_dest);

    size_t smemEnc = (size_t)(128 * 132 + 32 * 132) * 4 + 32 * 4;
    cudaFuncSetAttribute(encode_k, cudaFuncAttributeMaxDynamicSharedMemorySize, (int)smemEnc);
    encode_k<<<(N + 31) / 32, 256, smemEnc>>>(x, N, nullptr, W, b,
        (__half*)p_zh, (float*)p_zn2);
    encode_k<<<(M + 31) / 32, 256, smemEnc>>>(cx, M, (const int*)p_dest, W, b,
        (__half*)p_ch, (float*)p_cn);

    cudaFuncSetAttribute(nca_mma_k, cudaFuncAttributeMaxDynamicSharedMemorySize, SM_TOTAL);
    dim3 g(N / 128, NSPLIT);
    nca_mma_k<<<g, 512, SM_TOTAL>>>(
        (const __half*)p_zh, (const float*)p_zn2,
        (const __half*)p_ch, (const float*)p_cn,
        (const int*)p_cs, (float*)p_part, M, N);

    finalize_k<<<(N + 255) / 256, 256>>>((const float*)p_part, out, N);
}

// round 10
// speedup vs baseline: 1.6778x; 1.6778x over previous
#include <cuda_runtime.h>
#include <cuda_fp16.h>
#include <math.h>
#include <stdint.h>

#define FULLMASK 0xffffffffu
#define NCLS 10
#define MAXM 131072
#define MAXN 2048
#define NSPLIT 18
#define HB 256

// store z * log2(e) so ex2(-sqrt(sq')) = exp(-dist); norms * log2(e)^2
#define ZSCL 1.4426950408889634f
#define NSCL 2.081368981144074f

// ---------------- scratch (static device globals; no allocation) ------------
__device__ __half g_zc_h[MAXM * 128];
__device__ float  g_cn[MAXM];
__device__ __half g_z_h[MAXN * 128];
__device__ float  g_zn2[MAXN];
__device__ int    g_destMap[MAXM];
__device__ int    g_hist[(MAXM / HB) * NCLS];
__device__ int    g_classStart[NCLS + 1];
__device__ float  g_part[NSPLIT * MAXN * NCLS];

// ---------------- PTX helpers (baseline sm_80+ only) -------------------------
__device__ __forceinline__ uint32_t smem_u32(const void* p) {
    uint32_t a;
    asm("{ .reg .u64 t; cvta.to.shared.u64 t, %1; cvt.u32.u64 %0, t; }" : "=r"(a) : "l"(p));
    return a;
}

__device__ __forceinline__ uint32_t h2u(__half2 h) {
    union { __half2 h; uint32_t u; } cvt;
    cvt.h = h;
    return cvt.u;
}

#define CP16(saddr, gptr) \
    asm volatile("cp.async.cg.shared.global [%0], [%1], 16;" :: "r"(saddr), "l"(gptr))
#define CP_COMMIT() asm volatile("cp.async.commit_group;" ::: "memory")
#define CP_WAIT(n)  asm volatile("cp.async.wait_group %0;" :: "n"(n) : "memory")

#define LDSM4(r, addr) \
    asm volatile("ldmatrix.sync.aligned.m8n8.x4.shared.b16 {%0,%1,%2,%3}, [%4];" \
        : "=r"((r)[0]), "=r"((r)[1]), "=r"((r)[2]), "=r"((r)[3]) : "r"(addr))

#define MMA_F16(d, a, b0v, b1v) \
    asm volatile("mma.sync.aligned.m16n8k16.row.col.f32.f16.f16.f32 " \
        "{%0,%1,%2,%3},{%4,%5,%6,%7},{%8,%9},{%0,%1,%2,%3};" \
        : "+f"((d)[0]), "+f"((d)[1]), "+f"((d)[2]), "+f"((d)[3]) \
        : "r"((a)[0]), "r"((a)[1]), "r"((a)[2]), "r"((a)[3]), "r"(b0v), "r"(b1v))

// ---------------- counting sort by class (256-thread blocks) -----------------
__global__ __launch_bounds__(HB)
void hist_k(const int* __restrict__ y, int M, int* __restrict__ hist) {
    __shared__ int wc[HB / 32][NCLS];
    int tid = threadIdx.x, w = tid >> 5;
    int i = blockIdx.x * HB + tid;
    int c = (i < M) ? y[i] : -1;
#pragma unroll
    for (int cls = 0; cls < NCLS; ++cls) {
        unsigned b = __ballot_sync(FULLMASK, c == cls);
        if ((tid & 31) == 0) wc[w][cls] = __popc(b);
    }
    __syncthreads();
    if (tid < NCLS) {
        int s = 0;
#pragma unroll
        for (int ww = 0; ww < HB / 32; ++ww) s += wc[ww][tid];
        hist[blockIdx.x * NCLS + tid] = s;
    }
}

// parallel per-class exclusive scan over NB block-histograms (512 threads)
__global__ __launch_bounds__(512)
void scan_k(int* hist, int NB, int* classStart) {
    __shared__ int buf[512];
    __shared__ int carry[NCLS];
    int tid = threadIdx.x;
    if (tid < NCLS) carry[tid] = 0;
    __syncthreads();
    for (int c = 0; c < NCLS; ++c) {
        for (int b0 = 0; b0 < NB; b0 += 512) {
            int idx = b0 + tid;
            int v = (idx < NB) ? hist[idx * NCLS + c] : 0;
            buf[tid] = v;
            __syncthreads();
#pragma unroll
            for (int off = 1; off < 512; off <<= 1) {
                int t = (tid >= off) ? buf[tid - off] : 0;
                __syncthreads();
                buf[tid] += t;
                __syncthreads();
            }
            if (idx < NB) hist[idx * NCLS + c] = carry[c] + buf[tid] - v;
            __syncthreads();
            if (tid == 0) carry[c] += buf[511];
            __syncthreads();
        }
    }
    if (tid == 0) {
        int a = 0;
        for (int i = 0; i < NCLS; ++i) { classStart[i] = a; a += carry[i]; }
        classStart[NCLS] = a;
    }
}

__global__ __launch_bounds__(HB)
void scatter_k(const int* __restrict__ y, int M,
               const int* __restrict__ hist,
               const int* __restrict__ classStart,
               int* __restrict__ dest) {
    __shared__ int wc[HB / 32][NCLS];
    int tid = threadIdx.x, w = tid >> 5, lane = tid & 31;
    int i = blockIdx.x * HB + tid;
    int c = (i < M) ? y[i] : -1;
    unsigned mymask = 0;
#pragma unroll
    for (int cls = 0; cls < NCLS; ++cls) {
        unsigned b = __ballot_sync(FULLMASK, c == cls);
        if (lane == 0) wc[w][cls] = __popc(b);
        if (c == cls) mymask = b;
    }
    __syncthreads();
    if (tid < NCLS) {
        int run = 0;
#pragma unroll
        for (int ww = 0; ww < HB / 32; ++ww) {
            int t = wc[ww][tid];
            wc[ww][tid] = run;
            run += t;
        }
    }
    __syncthreads();
    if (i < M) {
        int rank = __popc(mymask & ((1u << lane) - 1u));
        dest[i] = classStart[c] + hist[blockIdx.x * NCLS + c] + wc[w][c] + rank;
    }
}

// ---------------- HMMA encoder: 128 rows x 128 dims per CTA ------------------
// smem layout (bytes)
#define E_XH    0        // 128x128 fp16 swizzled (also reused as zout, linear)
#define E_WH    32768    // 128x128 fp16 swizzled
#define E_BIAS  65536    // 128 f32
#define E_NRM   66048    // 128 f32
#define E_DST   66560    // 128 int
#define E_TOTAL 67072

__global__ __launch_bounds__(256, 2)
void encode_mma_k(const float* __restrict__ Xq, const float* __restrict__ Xc, int nbQ,
                  const int* __restrict__ destMap,
                  const float* __restrict__ W, const float* __restrict__ bias,
                  __half* __restrict__ zqH, float* __restrict__ zqN,
                  __half* __restrict__ zcH, float* __restrict__ zcN) {
    extern __shared__ char smc[];
    char* sm = smc;
    const uint32_t sb = smem_u32(sm);
    const int tid = threadIdx.x;
    const int w = tid >> 5, lane = tid & 31;
    const int warpM = w & 1, warpN = w >> 1;     // 2x4 grid, 64x32 warp tile
    const int q2 = (lane & 3) * 2;
    const int bid = blockIdx.x;
    const bool isQ = bid < nbQ;
    const int rowBase = (isQ ? bid : bid - nbQ) * 128;
    const float* src = isQ ? (Xq + (size_t)rowBase * 128) : (Xc + (size_t)rowBase * 128);
    __half* outH = isQ ? zqH : zcH;
    float* outN = isQ ? zqN : zcN;

    // load + convert X tile and W tile into swizzled fp16 smem
#pragma unroll
    for (int t = 0; t < 16; ++t) {
        int i4 = tid + t * 256;                  // float4 index, 0..4095
        int row = i4 >> 5, c4 = i4 & 31;
        float4 v = ((const float4*)src)[i4];
        uint32_t h0 = h2u(__floats2half2_rn(v.x, v.y));
        uint32_t h1 = h2u(__floats2half2_rn(v.z, v.w));
        uint32_t off = row * 256 + ((((uint32_t)(c4 >> 1)) ^ (row & 7)) << 4) + (c4 & 1) * 8;
        *(uint2*)(sm + E_XH + off) = make_uint2(h0, h1);
        float4 wv = ((const float4*)W)[i4];
        uint32_t w0 = h2u(__floats2half2_rn(wv.x, wv.y));
        uint32_t w1 = h2u(__floats2half2_rn(wv.z, wv.w));
        *(uint2*)(sm + E_WH + off) = make_uint2(w0, w1);
    }
    if (tid < 128) {
        ((float*)(sm + E_BIAS))[tid] = bias[tid];
        ((float*)(sm + E_NRM))[tid] = 0.f;
        ((int*)(sm + E_DST))[tid] = isQ ? (rowBase + tid) : destMap[rowBase + tid];
    }
    __syncthreads();

    // fragment addresses (identical math to main kernel)
    uint32_t aoff[4], asw[4];
#pragma unroll
    for (int mi = 0; mi < 4; ++mi) {
        int row = warpM * 64 + mi * 16 + (lane & 15);
        aoff[mi] = row * 256;
        asw[mi] = row & 7;
    }
    const uint32_t achb = lane >> 4;
    uint32_t boff[2], bsw[2];
#pragma unroll
    for (int g = 0; g < 2; ++g) {
        int row = warpN * 32 + g * 16 + (lane & 7) + ((lane >> 4) << 3);
        boff[g] = row * 256;
        bsw[g] = row & 7;
    }
    const uint32_t bchb = (lane >> 3) & 1;

    float acc[4][4][4];
#pragma unroll
    for (int mi = 0; mi < 4; ++mi)
#pragma unroll
        for (int ni = 0; ni < 4; ++ni)
#pragma unroll
            for (int k = 0; k < 4; ++k) acc[mi][ni][k] = 0.f;

#pragma unroll
    for (int k8 = 0; k8 < 8; ++k8) {
        uint32_t af[4][4], bf[2][4];
        uint32_t ca = 2 * k8 + achb, cbk = 2 * k8 + bchb;
#pragma unroll
        for (int mi = 0; mi < 4; ++mi)
            LDSM4(af[mi], sb + E_XH + aoff[mi] + ((ca ^ asw[mi]) << 4));
#pragma unroll
        for (int g = 0; g < 2; ++g)
            LDSM4(bf[g], sb + E_WH + boff[g] + ((cbk ^ bsw[g]) << 4));
#pragma unroll
        for (int mi = 0; mi < 4; ++mi)
#pragma unroll
            for (int ni = 0; ni < 4; ++ni) {
                int g = ni >> 1, p = (ni & 1) * 2;
                MMA_F16(acc[mi][ni], af[mi], bf[g][p], bf[g][p + 1]);
            }
    }
    __syncthreads();   // all ldmatrix reads done; E_XH reusable as zout

    // bias add, norms, store scaled fp16 z to linear zout (at E_XH)
    float bcol[4][2];
#pragma unroll
    for (int ni = 0; ni < 4; ++ni) {
        bcol[ni][0] = ((const float*)(sm + E_BIAS))[warpN * 32 + ni * 8 + q2];
        bcol[ni][1] = ((const float*)(sm + E_BIAS))[warpN * 32 + ni * 8 + q2 + 1];
    }
#pragma unroll
    for (int mi = 0; mi < 4; ++mi)
#pragma unroll
        for (int h = 0; h < 2; ++h) {
            int row = warpM * 64 + mi * 16 + (lane >> 2) + h * 8;
            float s = 0.f;
#pragma unroll
            for (int ni = 0; ni < 4; ++ni) {
                float v0 = acc[mi][ni][h * 2 + 0] + bcol[ni][0];
                float v1 = acc[mi][ni][h * 2 + 1] + bcol[ni][1];
                s += v0 * v0 + v1 * v1;
                __half2 hv = __floats2half2_rn(v0 * ZSCL, v1 * ZSCL);
                *(uint32_t*)(sm + E_XH + row * 256 + (warpN * 32 + ni * 8 + q2) * 2) = h2u(hv);
            }
            s += __shfl_xor_sync(FULLMASK, s, 1);
            s += __shfl_xor_sync(FULLMASK, s, 2);
            if ((lane & 3) == 0)
                atomicAdd((float*)(sm + E_NRM) + row, s);
        }
    __syncthreads();

    // coalesced writeback: warp w handles rows w*16 .. w*16+15
#pragma unroll
    for (int rr = 0; rr < 16; ++rr) {
        int row = w * 16 + rr;
        int d = ((const int*)(sm + E_DST))[row];
        uint2 v = *(uint2*)(sm + E_XH + row * 256 + lane * 8);
        ((uint2*)(outH + (size_t)d * 128))[lane] = v;
        if (lane == 0) outN[d] = ((const float*)(sm + E_NRM))[row] * NSCL;
    }
}

// ---------------- main: single-term fp16 HMMA dist + per-class numerators ----
#define SM_ZH    0
#define SM_B     32768     // 2 stages x 32768
#define SM_CN    98304     // 2 x 512
#define SM_SACC  99328     // 128*10 floats
#define SM_TOTAL 104448

__device__ __forceinline__ void issue_tile(uint32_t sbase, const uint4* __restrict__ g,
                                           int tid) {
#pragma unroll
    for (int t = 0; t < 8; ++t) {
        int idx = tid + t * 256;            // 0..2047, = row*16 + chunk
        int row = idx >> 4, c = idx & 15;
        uint32_t saddr = sbase + row * 256 + ((c ^ (row & 7)) << 4);
        CP16(saddr, g + idx);
    }
}

__global__ __launch_bounds__(256, 2)
void nca_mma_k(const __half* __restrict__ zh_g, const float* __restrict__ zn2,
               const __half* __restrict__ ch_g, const float* __restrict__ cn_g,
               const int* __restrict__ classStart,
               float* __restrict__ part, int M, int N) {
    extern __shared__ char smc[];
    char* sm = smc;
    const uint32_t sb = smem_u32(sm);
    const int tid = threadIdx.x;
    const int w = tid >> 5, lane = tid & 31;
    const int warpM = w & 1, warpN = w >> 1;   // 2 x 4 warp grid; 64 x 32 per warp
    const int q2 = (lane & 3) * 2;
    const int tile = blockIdx.x, split = blockIdx.y;
    const int chunksTotal = M >> 7;
    const int cpb = (chunksTotal + NSPLIT - 1) / NSPLIT;
    const int cLo = split * cpb;
    const int cHi = min(cLo + cpb, chunksTotal);
    const int nch = cHi - cLo;

    for (int i = tid; i < 128 * NCLS; i += 256) ((float*)(sm + SM_SACC))[i] = 0.f;

    int cs[NCLS + 1];
#pragma unroll
    for (int k = 0; k <= NCLS; ++k) cs[k] = classStart[k];

    float znr[4][2];
#pragma unroll
    for (int mi = 0; mi < 4; ++mi) {
        int r = tile * 128 + warpM * 64 + mi * 16 + (lane >> 2);
        znr[mi][0] = zn2[r];
        znr[mi][1] = zn2[r + 8];
    }

    // prologue
    issue_tile(sb + SM_ZH, (const uint4*)zh_g + (size_t)tile * 2048, tid);
    issue_tile(sb + SM_B, (const uint4*)ch_g + (size_t)cLo * 2048, tid);
    if (tid < 32) CP16(sb + SM_CN + tid * 16, (const float*)cn_g + (size_t)cLo * 128 + tid * 4);
    CP_COMMIT();
    if (nch > 1) {
        issue_tile(sb + SM_B + 32768, (const uint4*)ch_g + (size_t)(cLo + 1) * 2048, tid);
        if (tid < 32) CP16(sb + SM_CN + 512 + tid * 16,
                           (const float*)cn_g + (size_t)(cLo + 1) * 128 + tid * 4);
    }
    CP_COMMIT();

    // ldmatrix address precompute
    uint32_t aoff[4], asw[4];
#pragma unroll
    for (int mi = 0; mi < 4; ++mi) {
        int row = warpM * 64 + mi * 16 + (lane & 15);
        aoff[mi] = row * 256;
        asw[mi] = row & 7;
    }
    const uint32_t achb = lane >> 4;
    uint32_t boff[2], bsw[2];
#pragma unroll
    for (int g = 0; g < 2; ++g) {
        int row = warpN * 32 + g * 16 + (lane & 7) + ((lane >> 4) << 3);
        boff[g] = row * 256;
        bsw[g] = row & 7;
    }
    const uint32_t bchb = (lane >> 3) & 1;

    for (int i = 0; i < nch; ++i) {
        CP_WAIT(1);
        __syncthreads();                     // stage (i&1) data visible to all

        const int cb = i & 1;
        const uint32_t bbase = sb + SM_B + cb * 32768;
        const uint32_t abase = sb + SM_ZH;

        float acc[4][4][4];
#pragma unroll
        for (int mi = 0; mi < 4; ++mi)
#pragma unroll
            for (int ni = 0; ni < 4; ++ni)
#pragma unroll
                for (int k = 0; k < 4; ++k) acc[mi][ni][k] = 0.f;

#pragma unroll
        for (int k8 = 0; k8 < 8; ++k8) {
            uint32_t af[4][4], bf[2][4];
            uint32_t ca = 2 * k8 + achb, cbk = 2 * k8 + bchb;
#pragma unroll
            for (int mi = 0; mi < 4; ++mi)
                LDSM4(af[mi], abase + aoff[mi] + ((ca ^ asw[mi]) << 4));
#pragma unroll
            for (int g = 0; g < 2; ++g)
                LDSM4(bf[g], bbase + boff[g] + ((cbk ^ bsw[g]) << 4));
#pragma unroll
            for (int mi = 0; mi < 4; ++mi)
#pragma unroll
                for (int ni = 0; ni < 4; ++ni) {
                    int g = ni >> 1, p = (ni & 1) * 2;
                    MMA_F16(acc[mi][ni], af[mi], bf[g][p], bf[g][p + 1]);
                }
        }

        // pull candidate norms into registers BEFORE freeing the stage
        float cnv[4][2];
#pragma unroll
        for (int ni = 0; ni < 4; ++ni) {
            cnv[ni][0] = *(const float*)(sm + SM_CN + cb * 512 + (warpN * 32 + ni * 8 + q2) * 4);
            cnv[ni][1] = *(const float*)(sm + SM_CN + cb * 512 + (warpN * 32 + ni * 8 + q2 + 1) * 4);
        }

        __syncthreads();                     // all reads of stage cb done

        // prefetch chunk i+2 into stage cb; DMA overlaps the epilogue below
        if (i + 2 < nch) {
            issue_tile(sb + SM_B + cb * 32768,
                       (const uint4*)ch_g + (size_t)(cLo + i + 2) * 2048, tid);
            if (tid < 32) CP16(sb + SM_CN + cb * 512 + tid * 16,
                               (const float*)cn_g + (size_t)(cLo + i + 2) * 128 + tid * 4);
        }
        CP_COMMIT();

        // dist -> exp(-dist): sq already scaled by log2(e)^2 via ZSCL/NSCL
#pragma unroll
        for (int ni = 0; ni < 4; ++ni)
#pragma unroll
            for (int mi = 0; mi < 4; ++mi)
#pragma unroll
                for (int k = 0; k < 4; ++k) {
                    float base = znr[mi][k >> 1] + cnv[ni][k & 1];
                    float sq = fmaf(-2.f, acc[mi][ni][k], base);
                    float dd;
                    asm("sqrt.approx.f32 %0, %1;" : "=f"(dd) : "f"(sq));
                    float nd = -dd;
                    asm("ex2.approx.f32 %0, %1;" : "=f"(acc[mi][ni][k]) : "f"(nd));
                }

        // class-segmented accumulation (candidates sorted by class)
        const int wb = (cLo + i) * 128 + warpN * 32;
        int c0 = 0;
        while (c0 < NCLS - 1 && cs[c0 + 1] <= wb) ++c0;
        int c1 = c0;
        while (c1 < NCLS - 1 && cs[c1 + 1] < wb + 32) ++c1;
        if (c0 == c1) {
#pragma unroll
            for (int mi = 0; mi < 4; ++mi)
#pragma unroll
                for (int h = 0; h < 2; ++h) {
                    float s = 0.f;
#pragma unroll
                    for (int ni = 0; ni < 4; ++ni)
#pragma unroll
                        for (int j = 0; j < 2; ++j) s += acc[mi][ni][h * 2 + j];
                    s += __shfl_xor_sync(FULLMASK, s, 1);
                    s += __shfl_xor_sync(FULLMASK, s, 2);
                    if ((lane & 3) == 0) {
                        int r = warpM * 64 + mi * 16 + (lane >> 2) + h * 8;
                        atomicAdd((float*)(sm + SM_SACC) + r * NCLS + c0, s);
                    }
                }
        } else {
            for (int c = c0; c <= c1; ++c) {
                int lo = max(cs[c] - wb, 0), hi = min(cs[c + 1] - wb, 32);
#pragma unroll
                for (int mi = 0; mi < 4; ++mi)
#pragma unroll
                    for (int h = 0; h < 2; ++h) {
                        float s = 0.f;
#pragma unroll
                        for (int ni = 0; ni < 4; ++ni)
#pragma unroll
                            for (int j = 0; j < 2; ++j) {
                                int nl = ni * 8 + q2 + j;
                                s += (nl >= lo && nl < hi) ? acc[mi][ni][h * 2 + j] : 0.f;
                            }
                        s += __shfl_xor_sync(FULLMASK, s, 1);
                        s += __shfl_xor_sync(FULLMASK, s, 2);
                        if ((lane & 3) == 0) {
                            int r = warpM * 64 + mi * 16 + (lane >> 2) + h * 8;
                            atomicAdd((float*)(sm + SM_SACC) + r * NCLS + c, s);
                        }
                    }
            }
        }
    }

    __syncthreads();
    if (tid < 128) {
        int qg = tile * 128 + tid;
#pragma unroll
        for (int c = 0; c < NCLS; ++c)
            part[((size_t)split * N + qg) * NCLS + c] =
                ((float*)(sm + SM_SACC))[tid * NCLS + c];
    }
}

// ---------------- finalize: combine splits, normalize, log ------------------
__global__ void finalize_k(const float* __restrict__ part, float* __restrict__ out, int N) {
    int n = blockIdx.x * blockDim.x + threadIdx.x;
    if (n >= N) return;
    float t[NCLS];
#pragma unroll
    for (int c = 0; c < NCLS; ++c) t[c] = 0.f;
    for (int s = 0; s < NSPLIT; ++s)
#pragma unroll
        for (int c = 0; c < NCLS; ++c) t[c] += part[((size_t)s * N + n) * NCLS + c];
    float tot = 0.f;
#pragma unroll
    for (int c = 0; c < NCLS; ++c) tot += t[c];
    float inv = 1.f / tot;
#pragma unroll
    for (int c = 0; c < NCLS; ++c) out[n * NCLS + c] = logf(fmaf(t[c], inv, 1e-7f));
}

// ---------------- launch ----------------------------------------------------
extern "C" void kernel_launch(void* const* d_in, const int* in_sizes, int n_in,
                              void* d_out, int out_size) {
    const float* x  = (const float*)d_in[0];
    const float* cx = (const float*)d_in[1];
    const int*   cy = (const int*)d_in[2];
    const float* W  = (const float*)d_in[3];
    const float* b  = (const float*)d_in[4];
    int N = in_sizes[0] / 128;
    int M = in_sizes[2];
    float* out = (float*)d_out;

    void *p_ch, *p_cn, *p_zh, *p_zn2, *p_dest, *p_hist, *p_cs, *p_part;
    cudaGetSymbolAddress(&p_ch, g_zc_h);
    cudaGetSymbolAddress(&p_cn, g_cn);
    cudaGetSymbolAddress(&p_zh, g_z_h);
    cudaGetSymbolAddress(&p_zn2, g_zn2);
    cudaGetSymbolAddress(&p_dest, g_destMap);
    cudaGetSymbolAddress(&p_hist, g_hist);
    cudaGetSymbolAddress(&p_cs, g_classStart);
    cudaGetSymbolAddress(&p_part, g_part);

    int NB = (M + HB - 1) / HB;
    hist_k<<<NB, HB>>>(cy, M, (int*)p_hist);
    scan_k<<<1, 512>>>((int*)p_hist, NB, (int*)p_cs);
    scatter_k<<<NB, HB>>>(cy, M, (const int*)p_hist, (const int*)p_cs, (int*)p_dest);

    int nbQ = N / 128, nbC = M / 128;
    cudaFuncSetAttribute(encode_mma_k, cudaFuncAttributeMaxDynamicSharedMemorySize, E_TOTAL);
    encode_mma_k<<<nbQ + nbC, 256, E_TOTAL>>>(x, cx, nbQ, (const int*)p_dest, W, b,
        (__half*)p_zh, (float*)p_zn2, (__half*)p_ch, (float*)p_cn);

    cudaFuncSetAttribute(nca_mma_k, cudaFuncAttributeMaxDynamicSharedMemorySize, SM_TOTAL);
    dim3 g(N / 128, NSPLIT);
    nca_mma_k<<<g, 256, SM_TOTAL>>>(
        (const __half*)p_zh, (const float*)p_zn2,
        (const __half*)p_ch, (const float*)p_cn,
        (const int*)p_cs, (float*)p_part, M, N);

    finalize_k<<<(N + 255) / 256, 256>>>((const float*)p_part, out, N);
}

// round 11
// speedup vs baseline: 1.6832x; 1.0032x over previous
#include <cuda_runtime.h>
#include <cuda_fp16.h>
#include <math.h>
#include <stdint.h>

#define FULLMASK 0xffffffffu
#define NCLS 10
#define MAXM 131072
#define MAXN 2048
#define NSPLIT 18
#define HB 256

// store z * log2(e) so ex2(-sqrt(sq')) = exp(-dist); norms * log2(e)^2
#define ZSCL 1.4426950408889634f
#define NSCL 2.081368981144074f

// ---------------- scratch (static device globals; no allocation) ------------
__device__ __half g_zc_h[MAXM * 128];
__device__ float  g_cn[MAXM];
__device__ __half g_z_h[MAXN * 128];
__device__ float  g_zn2[MAXN];
__device__ int    g_destMap[MAXM];
__device__ int    g_hist[(MAXM / HB) * NCLS];
__device__ int    g_classStart[NCLS + 1];
__device__ float  g_part[NSPLIT * MAXN * NCLS];

// ---------------- PTX helpers (baseline sm_80+ only) -------------------------
__device__ __forceinline__ uint32_t smem_u32(const void* p) {
    uint32_t a;
    asm("{ .reg .u64 t; cvta.to.shared.u64 t, %1; cvt.u32.u64 %0, t; }" : "=r"(a) : "l"(p));
    return a;
}

__device__ __forceinline__ uint32_t h2u(__half2 h) {
    union { __half2 h; uint32_t u; } cvt;
    cvt.h = h;
    return cvt.u;
}

__device__ __forceinline__ float2 u2f2(uint32_t u) {
    union { __half2 h; uint32_t u; } cvt;
    cvt.u = u;
    return __half22float2(cvt.h);
}

#define CP16(saddr, gptr) \
    asm volatile("cp.async.cg.shared.global [%0], [%1], 16;" :: "r"(saddr), "l"(gptr))
#define CP_COMMIT() asm volatile("cp.async.commit_group;" ::: "memory")
#define CP_WAIT(n)  asm volatile("cp.async.wait_group %0;" :: "n"(n) : "memory")

#define LDSM4(r, addr) \
    asm volatile("ldmatrix.sync.aligned.m8n8.x4.shared.b16 {%0,%1,%2,%3}, [%4];" \
        : "=r"((r)[0]), "=r"((r)[1]), "=r"((r)[2]), "=r"((r)[3]) : "r"(addr))

#define MMA_F16(d, a, b0v, b1v) \
    asm volatile("mma.sync.aligned.m16n8k16.row.col.f32.f16.f16.f32 " \
        "{%0,%1,%2,%3},{%4,%5,%6,%7},{%8,%9},{%0,%1,%2,%3};" \
        : "+f"((d)[0]), "+f"((d)[1]), "+f"((d)[2]), "+f"((d)[3]) \
        : "r"((a)[0]), "r"((a)[1]), "r"((a)[2]), "r"((a)[3]), "r"(b0v), "r"(b1v))

// fp16-accumulate variant: D,C are 2 packed b32 regs (4 halves)
#define MMA_F16ACC(d, a, b0v, b1v) \
    asm volatile("mma.sync.aligned.m16n8k16.row.col.f16.f16.f16.f16 " \
        "{%0,%1},{%2,%3,%4,%5},{%6,%7},{%0,%1};" \
        : "+r"((d)[0]), "+r"((d)[1]) \
        : "r"((a)[0]), "r"((a)[1]), "r"((a)[2]), "r"((a)[3]), "r"(b0v), "r"(b1v))

// ---------------- counting sort by class (256-thread blocks) -----------------
__global__ __launch_bounds__(HB)
void hist_k(const int* __restrict__ y, int M, int* __restrict__ hist) {
    __shared__ int wc[HB / 32][NCLS];
    int tid = threadIdx.x, w = tid >> 5;
    int i = blockIdx.x * HB + tid;
    int c = (i < M) ? y[i] : -1;
#pragma unroll
    for (int cls = 0; cls < NCLS; ++cls) {
        unsigned b = __ballot_sync(FULLMASK, c == cls);
        if ((tid & 31) == 0) wc[w][cls] = __popc(b);
    }
    __syncthreads();
    if (tid < NCLS) {
        int s = 0;
#pragma unroll
        for (int ww = 0; ww < HB / 32; ++ww) s += wc[ww][tid];
        hist[blockIdx.x * NCLS + tid] = s;
    }
}

// parallel per-class exclusive scan over NB block-histograms (512 threads)
__global__ __launch_bounds__(512)
void scan_k(int* hist, int NB, int* classStart) {
    __shared__ int buf[512];
    __shared__ int carry[NCLS];
    int tid = threadIdx.x;
    if (tid < NCLS) carry[tid] = 0;
    __syncthreads();
    for (int c = 0; c < NCLS; ++c) {
        for (int b0 = 0; b0 < NB; b0 += 512) {
            int idx = b0 + tid;
            int v = (idx < NB) ? hist[idx * NCLS + c] : 0;
            buf[tid] = v;
            __syncthreads();
#pragma unroll
            for (int off = 1; off < 512; off <<= 1) {
                int t = (tid >= off) ? buf[tid - off] : 0;
                __syncthreads();
                buf[tid] += t;
                __syncthreads();
            }
            if (idx < NB) hist[idx * NCLS + c] = carry[c] + buf[tid] - v;
            __syncthreads();
            if (tid == 0) carry[c] += buf[511];
            __syncthreads();
        }
    }
    if (tid == 0) {
        int a = 0;
        for (int i = 0; i < NCLS; ++i) { classStart[i] = a; a += carry[i]; }
        classStart[NCLS] = a;
    }
}

__global__ __launch_bounds__(HB)
void scatter_k(const int* __restrict__ y, int M,
               const int* __restrict__ hist,
               const int* __restrict__ classStart,
               int* __restrict__ dest) {
    __shared__ int wc[HB / 32][NCLS];
    int tid = threadIdx.x, w = tid >> 5, lane = tid & 31;
    int i = blockIdx.x * HB + tid;
    int c = (i < M) ? y[i] : -1;
    unsigned mymask = 0;
#pragma unroll
    for (int cls = 0; cls < NCLS; ++cls) {
        unsigned b = __ballot_sync(FULLMASK, c == cls);
        if (lane == 0) wc[w][cls] = __popc(b);
        if (c == cls) mymask = b;
    }
    __syncthreads();
    if (tid < NCLS) {
        int run = 0;
#pragma unroll
        for (int ww = 0; ww < HB / 32; ++ww) {
            int t = wc[ww][tid];
            wc[ww][tid] = run;
            run += t;
        }
    }
    __syncthreads();
    if (i < M) {
        int rank = __popc(mymask & ((1u << lane) - 1u));
        dest[i] = classStart[c] + hist[blockIdx.x * NCLS + c] + wc[w][c] + rank;
    }
}

// ---------------- HMMA encoder: 128 rows x 128 dims per CTA ------------------
#define E_XH    0        // 128x128 fp16 swizzled (also reused as zout, linear)
#define E_WH    32768    // 128x128 fp16 swizzled
#define E_BIAS  65536    // 128 f32
#define E_NRM   66048    // 128 f32
#define E_DST   66560    // 128 int
#define E_TOTAL 67072

__global__ __launch_bounds__(256, 2)
void encode_mma_k(const float* __restrict__ Xq, const float* __restrict__ Xc, int nbQ,
                  const int* __restrict__ destMap,
                  const float* __restrict__ W, const float* __restrict__ bias,
                  __half* __restrict__ zqH, float* __restrict__ zqN,
                  __half* __restrict__ zcH, float* __restrict__ zcN) {
    extern __shared__ char smc[];
    char* sm = smc;
    const uint32_t sb = smem_u32(sm);
    const int tid = threadIdx.x;
    const int w = tid >> 5, lane = tid & 31;
    const int warpM = w & 1, warpN = w >> 1;     // 2x4 grid, 64x32 warp tile
    const int q2 = (lane & 3) * 2;
    const int bid = blockIdx.x;
    const bool isQ = bid < nbQ;
    const int rowBase = (isQ ? bid : bid - nbQ) * 128;
    const float* src = isQ ? (Xq + (size_t)rowBase * 128) : (Xc + (size_t)rowBase * 128);
    __half* outH = isQ ? zqH : zcH;
    float* outN = isQ ? zqN : zcN;

    // load + convert X tile and W tile into swizzled fp16 smem
#pragma unroll
    for (int t = 0; t < 16; ++t) {
        int i4 = tid + t * 256;                  // float4 index, 0..4095
        int row = i4 >> 5, c4 = i4 & 31;
        float4 v = ((const float4*)src)[i4];
        uint32_t h0 = h2u(__floats2half2_rn(v.x, v.y));
        uint32_t h1 = h2u(__floats2half2_rn(v.z, v.w));
        uint32_t off = row * 256 + ((((uint32_t)(c4 >> 1)) ^ (row & 7)) << 4) + (c4 & 1) * 8;
        *(uint2*)(sm + E_XH + off) = make_uint2(h0, h1);
        float4 wv = ((const float4*)W)[i4];
        uint32_t w0 = h2u(__floats2half2_rn(wv.x, wv.y));
        uint32_t w1 = h2u(__floats2half2_rn(wv.z, wv.w));
        *(uint2*)(sm + E_WH + off) = make_uint2(w0, w1);
    }
    if (tid < 128) {
        ((float*)(sm + E_BIAS))[tid] = bias[tid];
        ((float*)(sm + E_NRM))[tid] = 0.f;
        ((int*)(sm + E_DST))[tid] = isQ ? (rowBase + tid) : destMap[rowBase + tid];
    }
    __syncthreads();

    uint32_t aoff[4], asw[4];
#pragma unroll
    for (int mi = 0; mi < 4; ++mi) {
        int row = warpM * 64 + mi * 16 + (lane & 15);
        aoff[mi] = row * 256;
        asw[mi] = row & 7;
    }
    const uint32_t achb = lane >> 4;
    uint32_t boff[2], bsw[2];
#pragma unroll
    for (int g = 0; g < 2; ++g) {
        int row = warpN * 32 + g * 16 + (lane & 7) + ((lane >> 4) << 3);
        boff[g] = row * 256;
        bsw[g] = row & 7;
    }
    const uint32_t bchb = (lane >> 3) & 1;

    float acc[4][4][4];
#pragma unroll
    for (int mi = 0; mi < 4; ++mi)
#pragma unroll
        for (int ni = 0; ni < 4; ++ni)
#pragma unroll
            for (int k = 0; k < 4; ++k) acc[mi][ni][k] = 0.f;

#pragma unroll
    for (int k8 = 0; k8 < 8; ++k8) {
        uint32_t af[4][4], bf[2][4];
        uint32_t ca = 2 * k8 + achb, cbk = 2 * k8 + bchb;
#pragma unroll
        for (int mi = 0; mi < 4; ++mi)
            LDSM4(af[mi], sb + E_XH + aoff[mi] + ((ca ^ asw[mi]) << 4));
#pragma unroll
        for (int g = 0; g < 2; ++g)
            LDSM4(bf[g], sb + E_WH + boff[g] + ((cbk ^ bsw[g]) << 4));
#pragma unroll
        for (int mi = 0; mi < 4; ++mi)
#pragma unroll
            for (int ni = 0; ni < 4; ++ni) {
                int g = ni >> 1, p = (ni & 1) * 2;
                MMA_F16(acc[mi][ni], af[mi], bf[g][p], bf[g][p + 1]);
            }
    }
    __syncthreads();   // all ldmatrix reads done; E_XH reusable as zout

    float bcol[4][2];
#pragma unroll
    for (int ni = 0; ni < 4; ++ni) {
        bcol[ni][0] = ((const float*)(sm + E_BIAS))[warpN * 32 + ni * 8 + q2];
        bcol[ni][1] = ((const float*)(sm + E_BIAS))[warpN * 32 + ni * 8 + q2 + 1];
    }
#pragma unroll
    for (int mi = 0; mi < 4; ++mi)
#pragma unroll
        for (int h = 0; h < 2; ++h) {
            int row = warpM * 64 + mi * 16 + (lane >> 2) + h * 8;
            float s = 0.f;
#pragma unroll
            for (int ni = 0; ni < 4; ++ni) {
                float v0 = acc[mi][ni][h * 2 + 0] + bcol[ni][0];
                float v1 = acc[mi][ni][h * 2 + 1] + bcol[ni][1];
                s += v0 * v0 + v1 * v1;
                __half2 hv = __floats2half2_rn(v0 * ZSCL, v1 * ZSCL);
                *(uint32_t*)(sm + E_XH + row * 256 + (warpN * 32 + ni * 8 + q2) * 2) = h2u(hv);
            }
            s += __shfl_xor_sync(FULLMASK, s, 1);
            s += __shfl_xor_sync(FULLMASK, s, 2);
            if ((lane & 3) == 0)
                atomicAdd((float*)(sm + E_NRM) + row, s);
        }
    __syncthreads();

#pragma unroll
    for (int rr = 0; rr < 16; ++rr) {
        int row = w * 16 + rr;
        int d = ((const int*)(sm + E_DST))[row];
        uint2 v = *(uint2*)(sm + E_XH + row * 256 + lane * 8);
        ((uint2*)(outH + (size_t)d * 128))[lane] = v;
        if (lane == 0) outN[d] = ((const float*)(sm + E_NRM))[row] * NSCL;
    }
}

// ---------------- main: fp16-accum HMMA dist + per-class numerators ----------
#define SM_ZH    0
#define SM_B     32768     // 2 stages x 32768
#define SM_CN    98304     // 2 x 512
#define SM_SACC  99328     // 128*10 floats
#define SM_TOTAL 104448

__device__ __forceinline__ void issue_tile(uint32_t sbase, const uint4* __restrict__ g,
                                           int tid) {
#pragma unroll
    for (int t = 0; t < 8; ++t) {
        int idx = tid + t * 256;            // 0..2047, = row*16 + chunk
        int row = idx >> 4, c = idx & 15;
        uint32_t saddr = sbase + row * 256 + ((c ^ (row & 7)) << 4);
        CP16(saddr, g + idx);
    }
}

__global__ __launch_bounds__(256, 2)
void nca_mma_k(const __half* __restrict__ zh_g, const float* __restrict__ zn2,
               const __half* __restrict__ ch_g, const float* __restrict__ cn_g,
               const int* __restrict__ classStart,
               float* __restrict__ part, int M, int N) {
    extern __shared__ char smc[];
    char* sm = smc;
    const uint32_t sb = smem_u32(sm);
    const int tid = threadIdx.x;
    const int w = tid >> 5, lane = tid & 31;
    const int warpM = w & 1, warpN = w >> 1;   // 2 x 4 warp grid; 64 x 32 per warp
    const int q2 = (lane & 3) * 2;
    const int tile = blockIdx.x, split = blockIdx.y;
    const int chunksTotal = M >> 7;
    const int cpb = (chunksTotal + NSPLIT - 1) / NSPLIT;
    const int cLo = split * cpb;
    const int cHi = min(cLo + cpb, chunksTotal);
    const int nch = cHi - cLo;

    for (int i = tid; i < 128 * NCLS; i += 256) ((float*)(sm + SM_SACC))[i] = 0.f;

    int cs[NCLS + 1];
#pragma unroll
    for (int k = 0; k <= NCLS; ++k) cs[k] = classStart[k];

    float znr[4][2];
#pragma unroll
    for (int mi = 0; mi < 4; ++mi) {
        int r = tile * 128 + warpM * 64 + mi * 16 + (lane >> 2);
        znr[mi][0] = zn2[r];
        znr[mi][1] = zn2[r + 8];
    }

    // prologue
    issue_tile(sb + SM_ZH, (const uint4*)zh_g + (size_t)tile * 2048, tid);
    issue_tile(sb + SM_B, (const uint4*)ch_g + (size_t)cLo * 2048, tid);
    if (tid < 32) CP16(sb + SM_CN + tid * 16, (const float*)cn_g + (size_t)cLo * 128 + tid * 4);
    CP_COMMIT();
    if (nch > 1) {
        issue_tile(sb + SM_B + 32768, (const uint4*)ch_g + (size_t)(cLo + 1) * 2048, tid);
        if (tid < 32) CP16(sb + SM_CN + 512 + tid * 16,
                           (const float*)cn_g + (size_t)(cLo + 1) * 128 + tid * 4);
    }
    CP_COMMIT();

    // ldmatrix address precompute
    uint32_t aoff[4], asw[4];
#pragma unroll
    for (int mi = 0; mi < 4; ++mi) {
        int row = warpM * 64 + mi * 16 + (lane & 15);
        aoff[mi] = row * 256;
        asw[mi] = row & 7;
    }
    const uint32_t achb = lane >> 4;
    uint32_t boff[2], bsw[2];
#pragma unroll
    for (int g = 0; g < 2; ++g) {
        int row = warpN * 32 + g * 16 + (lane & 7) + ((lane >> 4) << 3);
        boff[g] = row * 256;
        bsw[g] = row & 7;
    }
    const uint32_t bchb = (lane >> 3) & 1;

    for (int i = 0; i < nch; ++i) {
        CP_WAIT(1);
        __syncthreads();                     // stage (i&1) data visible to all

        const int cb = i & 1;
        const uint32_t bbase = sb + SM_B + cb * 32768;
        const uint32_t abase = sb + SM_ZH;

        uint32_t acch[4][4][2];
#pragma unroll
        for (int mi = 0; mi < 4; ++mi)
#pragma unroll
            for (int ni = 0; ni < 4; ++ni) { acch[mi][ni][0] = 0u; acch[mi][ni][1] = 0u; }

#pragma unroll
        for (int k8 = 0; k8 < 8; ++k8) {
            uint32_t af[4][4], bf[2][4];
            uint32_t ca = 2 * k8 + achb, cbk = 2 * k8 + bchb;
#pragma unroll
            for (int mi = 0; mi < 4; ++mi)
                LDSM4(af[mi], abase + aoff[mi] + ((ca ^ asw[mi]) << 4));
#pragma unroll
            for (int g = 0; g < 2; ++g)
                LDSM4(bf[g], bbase + boff[g] + ((cbk ^ bsw[g]) << 4));
#pragma unroll
            for (int mi = 0; mi < 4; ++mi)
#pragma unroll
                for (int ni = 0; ni < 4; ++ni) {
                    int g = ni >> 1, p = (ni & 1) * 2;
                    MMA_F16ACC(acch[mi][ni], af[mi], bf[g][p], bf[g][p + 1]);
                }
        }

        // pull candidate norms into registers BEFORE freeing the stage
        float cnv[4][2];
#pragma unroll
        for (int ni = 0; ni < 4; ++ni) {
            cnv[ni][0] = *(const float*)(sm + SM_CN + cb * 512 + (warpN * 32 + ni * 8 + q2) * 4);
            cnv[ni][1] = *(const float*)(sm + SM_CN + cb * 512 + (warpN * 32 + ni * 8 + q2 + 1) * 4);
        }

        __syncthreads();                     // all reads of stage cb done

        // prefetch chunk i+2 into stage cb; DMA overlaps the epilogue below
        if (i + 2 < nch) {
            issue_tile(sb + SM_B + cb * 32768,
                       (const uint4*)ch_g + (size_t)(cLo + i + 2) * 2048, tid);
            if (tid < 32) CP16(sb + SM_CN + cb * 512 + tid * 16,
                               (const float*)cn_g + (size_t)(cLo + i + 2) * 128 + tid * 4);
        }
        CP_COMMIT();

        // unpack + dist -> exp(-dist)
        float acc[4][4][4];
#pragma unroll
        for (int mi = 0; mi < 4; ++mi)
#pragma unroll
            for (int ni = 0; ni < 4; ++ni) {
                float2 lo = u2f2(acch[mi][ni][0]);
                float2 hi = u2f2(acch[mi][ni][1]);
                acc[mi][ni][0] = lo.x; acc[mi][ni][1] = lo.y;
                acc[mi][ni][2] = hi.x; acc[mi][ni][3] = hi.y;
            }
#pragma unroll
        for (int ni = 0; ni < 4; ++ni)
#pragma unroll
            for (int mi = 0; mi < 4; ++mi)
#pragma unroll
                for (int k = 0; k < 4; ++k) {
                    float base = znr[mi][k >> 1] + cnv[ni][k & 1];
                    float sq = fmaf(-2.f, acc[mi][ni][k], base);
                    float dd;
                    asm("sqrt.approx.f32 %0, %1;" : "=f"(dd) : "f"(sq));
                    float nd = -dd;
                    asm("ex2.approx.f32 %0, %1;" : "=f"(acc[mi][ni][k]) : "f"(nd));
                }

        // class-segmented accumulation (candidates sorted by class)
        const int wb = (cLo + i) * 128 + warpN * 32;
        int c0 = 0;
        while (c0 < NCLS - 1 && cs[c0 + 1] <= wb) ++c0;
        int c1 = c0;
        while (c1 < NCLS - 1 && cs[c1 + 1] < wb + 32) ++c1;
        if (c0 == c1) {
#pragma unroll
            for (int mi = 0; mi < 4; ++mi)
#pragma unroll
                for (int h = 0; h < 2; ++h) {
                    float s = 0.f;
#pragma unroll
                    for (int ni = 0; ni < 4; ++ni)
#pragma unroll
                        for (int j = 0; j < 2; ++j) s += acc[mi][ni][h * 2 + j];
                    s += __shfl_xor_sync(FULLMASK, s, 1);
                    s += __shfl_xor_sync(FULLMASK, s, 2);
                    if ((lane & 3) == 0) {
                        int r = warpM * 64 + mi * 16 + (lane >> 2) + h * 8;
                        atomicAdd((float*)(sm + SM_SACC) + r * NCLS + c0, s);
                    }
                }
        } else {
            for (int c = c0; c <= c1; ++c) {
                int lo = max(cs[c] - wb, 0), hi = min(cs[c + 1] - wb, 32);
#pragma unroll
                for (int mi = 0; mi < 4; ++mi)
#pragma unroll
                    for (int h = 0; h < 2; ++h) {
                        float s = 0.f;
#pragma unroll
                        for (int ni = 0; ni < 4; ++ni)
#pragma unroll
                            for (int j = 0; j < 2; ++j) {
                                int nl = ni * 8 + q2 + j;
                                s += (nl >= lo && nl < hi) ? acc[mi][ni][h * 2 + j] : 0.f;
                            }
                        s += __shfl_xor_sync(FULLMASK, s, 1);
                        s += __shfl_xor_sync(FULLMASK, s, 2);
                        if ((lane & 3) == 0) {
                            int r = warpM * 64 + mi * 16 + (lane >> 2) + h * 8;
                            atomicAdd((float*)(sm + SM_SACC) + r * NCLS + c, s);
                        }
                    }
            }
        }
    }

    __syncthreads();
    if (tid < 128) {
        int qg = tile * 128 + tid;
#pragma unroll
        for (int c = 0; c < NCLS; ++c)
            part[((size_t)split * N + qg) * NCLS + c] =
                ((float*)(sm + SM_SACC))[tid * NCLS + c];
    }
}

// ---------------- finalize: combine splits, normalize, log ------------------
__global__ void finalize_k(const float* __restrict__ part, float* __restrict__ out, int N) {
    int n = blockIdx.x * blockDim.x + threadIdx.x;
    if (n >= N) return;
    float t[NCLS];
#pragma unroll
    for (int c = 0; c < NCLS; ++c) t[c] = 0.f;
    for (int s = 0; s < NSPLIT; ++s)
#pragma unroll
        for (int c = 0; c < NCLS; ++c) t[c] += part[((size_t)s * N + n) * NCLS + c];
    float tot = 0.f;
#pragma unroll
    for (int c = 0; c < NCLS; ++c) tot += t[c];
    float inv = 1.f / tot;
#pragma unroll
    for (int c = 0; c < NCLS; ++c) out[n * NCLS + c] = logf(fmaf(t[c], inv, 1e-7f));
}

// ---------------- launch ----------------------------------------------------
extern "C" void kernel_launch(void* const* d_in, const int* in_sizes, int n_in,
                              void* d_out, int out_size) {
    const float* x  = (const float*)d_in[0];
    const float* cx = (const float*)d_in[1];
    const int*   cy = (const int*)d_in[2];
    const float* W  = (const float*)d_in[3];
    const float* b  = (const float*)d_in[4];
    int N = in_sizes[0] / 128;
    int M = in_sizes[2];
    float* out = (float*)d_out;

    void *p_ch, *p_cn, *p_zh, *p_zn2, *p_dest, *p_hist, *p_cs, *p_part;
    cudaGetSymbolAddress(&p_ch, g_zc_h);
    cudaGetSymbolAddress(&p_cn, g_cn);
    cudaGetSymbolAddress(&p_zh, g_z_h);
    cudaGetSymbolAddress(&p_zn2, g_zn2);
    cudaGetSymbolAddress(&p_dest, g_destMap);
    cudaGetSymbolAddress(&p_hist, g_hist);
    cudaGetSymbolAddress(&p_cs, g_classStart);
    cudaGetSymbolAddress(&p_part, g_part);

    int NB = (M + HB - 1) / HB;
    hist_k<<<NB, HB>>>(cy, M, (int*)p_hist);
    scan_k<<<1, 512>>>((int*)p_hist, NB, (int*)p_cs);
    scatter_k<<<NB, HB>>>(cy, M, (const int*)p_hist, (const int*)p_cs, (int*)p_dest);

    int nbQ = N / 128, nbC = M / 128;
    cudaFuncSetAttribute(encode_mma_k, cudaFuncAttributeMaxDynamicSharedMemorySize, E_TOTAL);
    encode_mma_k<<<nbQ + nbC, 256, E_TOTAL>>>(x, cx, nbQ, (const int*)p_dest, W, b,
        (__half*)p_zh, (float*)p_zn2, (__half*)p_ch, (float*)p_cn);

    cudaFuncSetAttribute(nca_mma_k, cudaFuncAttributeMaxDynamicSharedMemorySize, SM_TOTAL);
    dim3 g(N / 128, NSPLIT);
    nca_mma_k<<<g, 256, SM_TOTAL>>>(
        (const __half*)p_zh, (const float*)p_zn2,
        (const __half*)p_ch, (const float*)p_cn,
        (const int*)p_cs, (float*)p_part, M, N);

    finalize_k<<<(N + 255) / 256, 256>>>((const float*)p_part, out, N);
}

// round 12
// speedup vs baseline: 1.7641x; 1.0481x over previous
#include <cuda_runtime.h>
#include <cuda_fp16.h>
#include <math.h>
#include <stdint.h>

#define FULLMASK 0xffffffffu
#define NCLS 10
#define MAXM 131072
#define MAXN 2048
#define NSPLIT 18
#define HB 256

// store z * log2(e) so ex2(-sqrt(sq')) = exp(-dist); norms * log2(e)^2
#define ZSCL 1.4426950408889634f
#define NSCL 2.081368981144074f

// ---------------- scratch (static device globals; no allocation) ------------
__device__ __half g_zc_h[MAXM * 128];
__device__ float  g_cn[MAXM];
__device__ __half g_z_h[MAXN * 128];
__device__ float  g_zn2[MAXN];
__device__ int    g_destMap[MAXM];
__device__ int    g_hist[(MAXM / HB) * NCLS];
__device__ int    g_classStart[NCLS + 1];
__device__ float  g_part[NSPLIT * MAXN * NCLS];

// ---------------- PTX helpers (baseline sm_80+ only) -------------------------
__device__ __forceinline__ uint32_t smem_u32(const void* p) {
    uint32_t a;
    asm("{ .reg .u64 t; cvta.to.shared.u64 t, %1; cvt.u32.u64 %0, t; }" : "=r"(a) : "l"(p));
    return a;
}

__device__ __forceinline__ uint32_t h2u(__half2 h) {
    union { __half2 h; uint32_t u; } cvt;
    cvt.h = h;
    return cvt.u;
}

__device__ __forceinline__ float2 u2f2(uint32_t u) {
    union { __half2 h; uint32_t u; } cvt;
    cvt.u = u;
    return __half22float2(cvt.h);
}

#define CP16(saddr, gptr) \
    asm volatile("cp.async.cg.shared.global [%0], [%1], 16;" :: "r"(saddr), "l"(gptr))
#define CP_COMMIT() asm volatile("cp.async.commit_group;" ::: "memory")
#define CP_WAIT(n)  asm volatile("cp.async.wait_group %0;" :: "n"(n) : "memory")

#define LDSM4(r, addr) \
    asm volatile("ldmatrix.sync.aligned.m8n8.x4.shared.b16 {%0,%1,%2,%3}, [%4];" \
        : "=r"((r)[0]), "=r"((r)[1]), "=r"((r)[2]), "=r"((r)[3]) : "r"(addr))

#define MMA_F16(d, a, b0v, b1v) \
    asm volatile("mma.sync.aligned.m16n8k16.row.col.f32.f16.f16.f32 " \
        "{%0,%1,%2,%3},{%4,%5,%6,%7},{%8,%9},{%0,%1,%2,%3};" \
        : "+f"((d)[0]), "+f"((d)[1]), "+f"((d)[2]), "+f"((d)[3]) \
        : "r"((a)[0]), "r"((a)[1]), "r"((a)[2]), "r"((a)[3]), "r"(b0v), "r"(b1v))

// fp16-accumulate variant: D,C are 2 packed b32 regs (4 halves)
#define MMA_F16ACC(d, a, b0v, b1v) \
    asm volatile("mma.sync.aligned.m16n8k16.row.col.f16.f16.f16.f16 " \
        "{%0,%1},{%2,%3,%4,%5},{%6,%7},{%0,%1};" \
        : "+r"((d)[0]), "+r"((d)[1]) \
        : "r"((a)[0]), "r"((a)[1]), "r"((a)[2]), "r"((a)[3]), "r"(b0v), "r"(b1v))

// ---------------- counting sort by class (256-thread blocks) -----------------
__global__ __launch_bounds__(HB)
void hist_k(const int* __restrict__ y, int M, int* __restrict__ hist) {
    __shared__ int wc[HB / 32][NCLS];
    int tid = threadIdx.x, w = tid >> 5;
    int i = blockIdx.x * HB + tid;
    int c = (i < M) ? y[i] : -1;
#pragma unroll
    for (int cls = 0; cls < NCLS; ++cls) {
        unsigned b = __ballot_sync(FULLMASK, c == cls);
        if ((tid & 31) == 0) wc[w][cls] = __popc(b);
    }
    __syncthreads();
    if (tid < NCLS) {
        int s = 0;
#pragma unroll
        for (int ww = 0; ww < HB / 32; ++ww) s += wc[ww][tid];
        hist[blockIdx.x * NCLS + tid] = s;
    }
}

// parallel per-class exclusive scan over NB block-histograms (512 threads)
__global__ __launch_bounds__(512)
void scan_k(int* hist, int NB, int* classStart) {
    __shared__ int buf[512];
    __shared__ int carry[NCLS];
    int tid = threadIdx.x;
    if (tid < NCLS) carry[tid] = 0;
    __syncthreads();
    for (int c = 0; c < NCLS; ++c) {
        for (int b0 = 0; b0 < NB; b0 += 512) {
            int idx = b0 + tid;
            int v = (idx < NB) ? hist[idx * NCLS + c] : 0;
            buf[tid] = v;
            __syncthreads();
#pragma unroll
            for (int off = 1; off < 512; off <<= 1) {
                int t = (tid >= off) ? buf[tid - off] : 0;
                __syncthreads();
                buf[tid] += t;
                __syncthreads();
            }
            if (idx < NB) hist[idx * NCLS + c] = carry[c] + buf[tid] - v;
            __syncthreads();
            if (tid == 0) carry[c] += buf[511];
            __syncthreads();
        }
    }
    if (tid == 0) {
        int a = 0;
        for (int i = 0; i < NCLS; ++i) { classStart[i] = a; a += carry[i]; }
        classStart[NCLS] = a;
    }
}

__global__ __launch_bounds__(HB)
void scatter_k(const int* __restrict__ y, int M,
               const int* __restrict__ hist,
               const int* __restrict__ classStart,
               int* __restrict__ dest) {
    __shared__ int wc[HB / 32][NCLS];
    int tid = threadIdx.x, w = tid >> 5, lane = tid & 31;
    int i = blockIdx.x * HB + tid;
    int c = (i < M) ? y[i] : -1;
    unsigned mymask = 0;
#pragma unroll
    for (int cls = 0; cls < NCLS; ++cls) {
        unsigned b = __ballot_sync(FULLMASK, c == cls);
        if (lane == 0) wc[w][cls] = __popc(b);
        if (c == cls) mymask = b;
    }
    __syncthreads();
    if (tid < NCLS) {
        int run = 0;
#pragma unroll
        for (int ww = 0; ww < HB / 32; ++ww) {
            int t = wc[ww][tid];
            wc[ww][tid] = run;
            run += t;
        }
    }
    __syncthreads();
    if (i < M) {
        int rank = __popc(mymask & ((1u << lane) - 1u));
        dest[i] = classStart[c] + hist[blockIdx.x * NCLS + c] + wc[w][c] + rank;
    }
}

// ---------------- HMMA encoder: 128 rows x 128 dims per CTA ------------------
#define E_XH    0        // 128x128 fp16 swizzled (also reused as zout, linear)
#define E_WH    32768    // 128x128 fp16 swizzled
#define E_BIAS  65536    // 128 f32
#define E_NRM   66048    // 128 f32
#define E_DST   66560    // 128 int
#define E_TOTAL 67072

__global__ __launch_bounds__(256, 2)
void encode_mma_k(const float* __restrict__ Xq, const float* __restrict__ Xc, int nbQ,
                  const int* __restrict__ destMap,
                  const float* __restrict__ W, const float* __restrict__ bias,
                  __half* __restrict__ zqH, float* __restrict__ zqN,
                  __half* __restrict__ zcH, float* __restrict__ zcN) {
    extern __shared__ char smc[];
    char* sm = smc;
    const uint32_t sb = smem_u32(sm);
    const int tid = threadIdx.x;
    const int w = tid >> 5, lane = tid & 31;
    const int warpM = w & 1, warpN = w >> 1;     // 2x4 grid, 64x32 warp tile
    const int q2 = (lane & 3) * 2;
    const int bid = blockIdx.x;
    const bool isQ = bid < nbQ;
    const int rowBase = (isQ ? bid : bid - nbQ) * 128;
    const float* src = isQ ? (Xq + (size_t)rowBase * 128) : (Xc + (size_t)rowBase * 128);
    __half* outH = isQ ? zqH : zcH;
    float* outN = isQ ? zqN : zcN;

    // load + convert X tile and W tile into swizzled fp16 smem
#pragma unroll
    for (int t = 0; t < 16; ++t) {
        int i4 = tid + t * 256;                  // float4 index, 0..4095
        int row = i4 >> 5, c4 = i4 & 31;
        float4 v = ((const float4*)src)[i4];
        uint32_t h0 = h2u(__floats2half2_rn(v.x, v.y));
        uint32_t h1 = h2u(__floats2half2_rn(v.z, v.w));
        uint32_t off = row * 256 + ((((uint32_t)(c4 >> 1)) ^ (row & 7)) << 4) + (c4 & 1) * 8;
        *(uint2*)(sm + E_XH + off) = make_uint2(h0, h1);
        float4 wv = ((const float4*)W)[i4];
        uint32_t w0 = h2u(__floats2half2_rn(wv.x, wv.y));
        uint32_t w1 = h2u(__floats2half2_rn(wv.z, wv.w));
        *(uint2*)(sm + E_WH + off) = make_uint2(w0, w1);
    }
    if (tid < 128) {
        ((float*)(sm + E_BIAS))[tid] = bias[tid];
        ((float*)(sm + E_NRM))[tid] = 0.f;
        ((int*)(sm + E_DST))[tid] = isQ ? (rowBase + tid) : destMap[rowBase + tid];
    }
    __syncthreads();

    uint32_t aoff[4], asw[4];
#pragma unroll
    for (int mi = 0; mi < 4; ++mi) {
        int row = warpM * 64 + mi * 16 + (lane & 15);
        aoff[mi] = row * 256;
        asw[mi] = row & 7;
    }
    const uint32_t achb = lane >> 4;
    uint32_t boff[2], bsw[2];
#pragma unroll
    for (int g = 0; g < 2; ++g) {
        int row = warpN * 32 + g * 16 + (lane & 7) + ((lane >> 4) << 3);
        boff[g] = row * 256;
        bsw[g] = row & 7;
    }
    const uint32_t bchb = (lane >> 3) & 1;

    float acc[4][4][4];
#pragma unroll
    for (int mi = 0; mi < 4; ++mi)
#pragma unroll
        for (int ni = 0; ni < 4; ++ni)
#pragma unroll
            for (int k = 0; k < 4; ++k) acc[mi][ni][k] = 0.f;

#pragma unroll
    for (int k8 = 0; k8 < 8; ++k8) {
        uint32_t af[4][4], bf[2][4];
        uint32_t ca = 2 * k8 + achb, cbk = 2 * k8 + bchb;
#pragma unroll
        for (int mi = 0; mi < 4; ++mi)
            LDSM4(af[mi], sb + E_XH + aoff[mi] + ((ca ^ asw[mi]) << 4));
#pragma unroll
        for (int g = 0; g < 2; ++g)
            LDSM4(bf[g], sb + E_WH + boff[g] + ((cbk ^ bsw[g]) << 4));
#pragma unroll
        for (int mi = 0; mi < 4; ++mi)
#pragma unroll
            for (int ni = 0; ni < 4; ++ni) {
                int g = ni >> 1, p = (ni & 1) * 2;
                MMA_F16(acc[mi][ni], af[mi], bf[g][p], bf[g][p + 1]);
            }
    }
    __syncthreads();   // all ldmatrix reads done; E_XH reusable as zout

    float bcol[4][2];
#pragma unroll
    for (int ni = 0; ni < 4; ++ni) {
        bcol[ni][0] = ((const float*)(sm + E_BIAS))[warpN * 32 + ni * 8 + q2];
        bcol[ni][1] = ((const float*)(sm + E_BIAS))[warpN * 32 + ni * 8 + q2 + 1];
    }
#pragma unroll
    for (int mi = 0; mi < 4; ++mi)
#pragma unroll
        for (int h = 0; h < 2; ++h) {
            int row = warpM * 64 + mi * 16 + (lane >> 2) + h * 8;
            float s = 0.f;
#pragma unroll
            for (int ni = 0; ni < 4; ++ni) {
                float v0 = acc[mi][ni][h * 2 + 0] + bcol[ni][0];
                float v1 = acc[mi][ni][h * 2 + 1] + bcol[ni][1];
                s += v0 * v0 + v1 * v1;
                __half2 hv = __floats2half2_rn(v0 * ZSCL, v1 * ZSCL);
                *(uint32_t*)(sm + E_XH + row * 256 + (warpN * 32 + ni * 8 + q2) * 2) = h2u(hv);
            }
            s += __shfl_xor_sync(FULLMASK, s, 1);
            s += __shfl_xor_sync(FULLMASK, s, 2);
            if ((lane & 3) == 0)
                atomicAdd((float*)(sm + E_NRM) + row, s);
        }
    __syncthreads();

#pragma unroll
    for (int rr = 0; rr < 16; ++rr) {
        int row = w * 16 + rr;
        int d = ((const int*)(sm + E_DST))[row];
        uint2 v = *(uint2*)(sm + E_XH + row * 256 + lane * 8);
        ((uint2*)(outH + (size_t)d * 128))[lane] = v;
        if (lane == 0) outN[d] = ((const float*)(sm + E_NRM))[row] * NSCL;
    }
}

// ---------------- main: fp16-acc HMMA, per-pair sync + per-pair prefetch -----
#define SM_ZH    0
#define SM_B     32768     // 2 stages x 32768
#define SM_CN    98304     // 2 x 512
#define SM_SACC  99328     // 128*10 floats
#define SM_TOTAL 104448

#define BAR_PAIR(pid) asm volatile("bar.sync %0, 64;" :: "r"(1 + (pid)) : "memory")

// CTA-wide copy of one 128x128 fp16 tile (32KB) into swizzled smem
__device__ __forceinline__ void issue_tile(uint32_t sbase, const uint4* __restrict__ g,
                                           int tid) {
#pragma unroll
    for (int t = 0; t < 8; ++t) {
        int idx = tid + t * 256;            // 0..2047, = row*16 + chunk
        int row = idx >> 4, c = idx & 15;
        uint32_t saddr = sbase + row * 256 + ((c ^ (row & 7)) << 4);
        CP16(saddr, g + idx);
    }
}

// pair-partitioned copy: pair p loads rows [p*32, p*32+32) (8KB, 64 threads)
__device__ __forceinline__ void issue_pair_tile(uint32_t sbase, const uint4* __restrict__ g,
                                                int pid, int tid64) {
#pragma unroll
    for (int t = 0; t < 8; ++t) {
        int idx = pid * 512 + tid64 + t * 64;   // uint4 index = row*16 + chunk
        int row = idx >> 4, c = idx & 15;
        uint32_t saddr = sbase + row * 256 + ((c ^ (row & 7)) << 4);
        CP16(saddr, g + idx);
    }
}

__global__ __launch_bounds__(256, 2)
void nca_mma_k(const __half* __restrict__ zh_g, const float* __restrict__ zn2,
               const __half* __restrict__ ch_g, const float* __restrict__ cn_g,
               const int* __restrict__ classStart,
               float* __restrict__ part, int M, int N) {
    extern __shared__ char smc[];
    char* sm = smc;
    const uint32_t sb = smem_u32(sm);
    const int tid = threadIdx.x;
    const int w = tid >> 5, lane = tid & 31;
    const int warpM = w & 1, warpN = w >> 1;   // 2 x 4 warp grid; 64 x 32 per warp
    const int pid = tid >> 6;                   // pair id == warpN
    const int tid64 = tid & 63;
    const int q2 = (lane & 3) * 2;
    const int tile = blockIdx.x, split = blockIdx.y;
    const int chunksTotal = M >> 7;
    const int cpb = (chunksTotal + NSPLIT - 1) / NSPLIT;
    const int cLo = split * cpb;
    const int cHi = min(cLo + cpb, chunksTotal);
    const int nch = cHi - cLo;

    for (int i = tid; i < 128 * NCLS; i += 256) ((float*)(sm + SM_SACC))[i] = 0.f;

    int cs[NCLS + 1];
#pragma unroll
    for (int k = 0; k <= NCLS; ++k) cs[k] = classStart[k];

    float znr[4][2];
#pragma unroll
    for (int mi = 0; mi < 4; ++mi) {
        int r = tile * 128 + warpM * 64 + mi * 16 + (lane >> 2);
        znr[mi][0] = zn2[r];
        znr[mi][1] = zn2[r + 8];
    }

    // prologue: z CTA-wide; stage0/stage1 + cn partitioned per pair
    issue_tile(sb + SM_ZH, (const uint4*)zh_g + (size_t)tile * 2048, tid);
    issue_pair_tile(sb + SM_B, (const uint4*)ch_g + (size_t)cLo * 2048, pid, tid64);
    if (tid64 < 8) CP16(sb + SM_CN + pid * 128 + tid64 * 16,
                        (const float*)cn_g + (size_t)cLo * 128 + pid * 32 + tid64 * 4);
    CP_COMMIT();
    if (nch > 1) {
        issue_pair_tile(sb + SM_B + 32768, (const uint4*)ch_g + (size_t)(cLo + 1) * 2048,
                        pid, tid64);
        if (tid64 < 8) CP16(sb + SM_CN + 512 + pid * 128 + tid64 * 16,
                            (const float*)cn_g + (size_t)(cLo + 1) * 128 + pid * 32 + tid64 * 4);
    }
    CP_COMMIT();

    // ldmatrix address precompute
    uint32_t aoff[4], asw[4];
#pragma unroll
    for (int mi = 0; mi < 4; ++mi) {
        int row = warpM * 64 + mi * 16 + (lane & 15);
        aoff[mi] = row * 256;
        asw[mi] = row & 7;
    }
    const uint32_t achb = lane >> 4;
    uint32_t boff[2], bsw[2];
#pragma unroll
    for (int g = 0; g < 2; ++g) {
        int row = warpN * 32 + g * 16 + (lane & 7) + ((lane >> 4) << 3);
        boff[g] = row * 256;
        bsw[g] = row & 7;
    }
    const uint32_t bchb = (lane >> 3) & 1;

    CP_WAIT(1);
    __syncthreads();                 // z + stage0 + sacc zero visible CTA-wide

    for (int i = 0; i < nch; ++i) {
        if (i > 0) {
            CP_WAIT(1);
            BAR_PAIR(pid);           // pair's stage (i&1) slice visible
        }

        const int cb = i & 1;
        const uint32_t bbase = sb + SM_B + cb * 32768;
        const uint32_t abase = sb + SM_ZH;

        uint32_t acch[4][4][2];
#pragma unroll
        for (int mi = 0; mi < 4; ++mi)
#pragma unroll
            for (int ni = 0; ni < 4; ++ni) { acch[mi][ni][0] = 0u; acch[mi][ni][1] = 0u; }

#pragma unroll
        for (int k8 = 0; k8 < 8; ++k8) {
            uint32_t af[4][4], bf[2][4];
            uint32_t ca = 2 * k8 + achb, cbk = 2 * k8 + bchb;
#pragma unroll
            for (int mi = 0; mi < 4; ++mi)
                LDSM4(af[mi], abase + aoff[mi] + ((ca ^ asw[mi]) << 4));
#pragma unroll
            for (int g = 0; g < 2; ++g)
                LDSM4(bf[g], bbase + boff[g] + ((cbk ^ bsw[g]) << 4));
#pragma unroll
            for (int mi = 0; mi < 4; ++mi)
#pragma unroll
                for (int ni = 0; ni < 4; ++ni) {
                    int g = ni >> 1, p = (ni & 1) * 2;
                    MMA_F16ACC(acch[mi][ni], af[mi], bf[g][p], bf[g][p + 1]);
                }
        }

        // pull candidate norms into registers BEFORE freeing the stage
        float cnv[4][2];
#pragma unroll
        for (int ni = 0; ni < 4; ++ni) {
            cnv[ni][0] = *(const float*)(sm + SM_CN + cb * 512 + (warpN * 32 + ni * 8 + q2) * 4);
            cnv[ni][1] = *(const float*)(sm + SM_CN + cb * 512 + (warpN * 32 + ni * 8 + q2 + 1) * 4);
        }

        BAR_PAIR(pid);               // pair's reads of its stage-cb slice done

        // prefetch chunk i+2 into pair's slice of stage cb; overlaps epilogue
        if (i + 2 < nch) {
            issue_pair_tile(sb + SM_B + cb * 32768,
                            (const uint4*)ch_g + (size_t)(cLo + i + 2) * 2048, pid, tid64);
            if (tid64 < 8) CP16(sb + SM_CN + cb * 512 + pid * 128 + tid64 * 16,
                                (const float*)cn_g + (size_t)(cLo + i + 2) * 128 +
                                pid * 32 + tid64 * 4);
        }
        CP_COMMIT();

        // unpack + dist -> exp(-dist)
        float acc[4][4][4];
#pragma unroll
        for (int mi = 0; mi < 4; ++mi)
#pragma unroll
            for (int ni = 0; ni < 4; ++ni) {
                float2 lo = u2f2(acch[mi][ni][0]);
                float2 hi = u2f2(acch[mi][ni][1]);
                acc[mi][ni][0] = lo.x; acc[mi][ni][1] = lo.y;
                acc[mi][ni][2] = hi.x; acc[mi][ni][3] = hi.y;
            }
#pragma unroll
        for (int ni = 0; ni < 4; ++ni)
#pragma unroll
            for (int mi = 0; mi < 4; ++mi)
#pragma unroll
                for (int k = 0; k < 4; ++k) {
                    float base = znr[mi][k >> 1] + cnv[ni][k & 1];
                    float sq = fmaf(-2.f, acc[mi][ni][k], base);
                    float dd;
                    asm("sqrt.approx.f32 %0, %1;" : "=f"(dd) : "f"(sq));
                    float nd = -dd;
                    asm("ex2.approx.f32 %0, %1;" : "=f"(acc[mi][ni][k]) : "f"(nd));
                }

        // class-segmented accumulation (candidates sorted by class)
        const int wb = (cLo + i) * 128 + warpN * 32;
        int c0 = 0;
        while (c0 < NCLS - 1 && cs[c0 + 1] <= wb) ++c0;
        int c1 = c0;
        while (c1 < NCLS - 1 && cs[c1 + 1] < wb + 32) ++c1;
        if (c0 == c1) {
#pragma unroll
            for (int mi = 0; mi < 4; ++mi)
#pragma unroll
                for (int h = 0; h < 2; ++h) {
                    float s = 0.f;
#pragma unroll
                    for (int ni = 0; ni < 4; ++ni)
#pragma unroll
                        for (int j = 0; j < 2; ++j) s += acc[mi][ni][h * 2 + j];
                    s += __shfl_xor_sync(FULLMASK, s, 1);
                    s += __shfl_xor_sync(FULLMASK, s, 2);
                    if ((lane & 3) == 0) {
                        int r = warpM * 64 + mi * 16 + (lane >> 2) + h * 8;
                        atomicAdd((float*)(sm + SM_SACC) + r * NCLS + c0, s);
                    }
                }
        } else {
            for (int c = c0; c <= c1; ++c) {
                int lo = max(cs[c] - wb, 0), hi = min(cs[c + 1] - wb, 32);
#pragma unroll
                for (int mi = 0; mi < 4; ++mi)
#pragma unroll
                    for (int h = 0; h < 2; ++h) {
                        float s = 0.f;
#pragma unroll
                        for (int ni = 0; ni < 4; ++ni)
#pragma unroll
                            for (int j = 0; j < 2; ++j) {
                                int nl = ni * 8 + q2 + j;
                                s += (nl >= lo && nl < hi) ? acc[mi][ni][h * 2 + j] : 0.f;
                            }
                        s += __shfl_xor_sync(FULLMASK, s, 1);
                        s += __shfl_xor_sync(FULLMASK, s, 2);
                        if ((lane & 3) == 0) {
                            int r = warpM * 64 + mi * 16 + (lane >> 2) + h * 8;
                            atomicAdd((float*)(sm + SM_SACC) + r * NCLS + c, s);
                        }
                    }
            }
        }
    }

    __syncthreads();                 // all pairs' atomicAdds complete
    if (tid < 128) {
        int qg = tile * 128 + tid;
#pragma unroll
        for (int c = 0; c < NCLS; ++c)
            part[((size_t)split * N + qg) * NCLS + c] =
                ((float*)(sm + SM_SACC))[tid * NCLS + c];
    }
}

// ---------------- finalize: combine splits, normalize, log ------------------
__global__ void finalize_k(const float* __restrict__ part, float* __restrict__ out, int N) {
    int n = blockIdx.x * blockDim.x + threadIdx.x;
    if (n >= N) return;
    float t[NCLS];
#pragma unroll
    for (int c = 0; c < NCLS; ++c) t[c] = 0.f;
    for (int s = 0; s < NSPLIT; ++s)
#pragma unroll
        for (int c = 0; c < NCLS; ++c) t[c] += part[((size_t)s * N + n) * NCLS + c];
    float tot = 0.f;
#pragma unroll
    for (int c = 0; c < NCLS; ++c) tot += t[c];
    float inv = 1.f / tot;
#pragma unroll
    for (int c = 0; c < NCLS; ++c) out[n * NCLS + c] = logf(fmaf(t[c], inv, 1e-7f));
}

// ---------------- launch ----------------------------------------------------
extern "C" void kernel_launch(void* const* d_in, const int* in_sizes, int n_in,
                              void* d_out, int out_size) {
    const float* x  = (const float*)d_in[0];
    const float* cx = (const float*)d_in[1];
    const int*   cy = (const int*)d_in[2];
    const float* W  = (const float*)d_in[3];
    const float* b  = (const float*)d_in[4];
    int N = in_sizes[0] / 128;
    int M = in_sizes[2];
    float* out = (float*)d_out;

    void *p_ch, *p_cn, *p_zh, *p_zn2, *p_dest, *p_hist, *p_cs, *p_part;
    cudaGetSymbolAddress(&p_ch, g_zc_h);
    cudaGetSymbolAddress(&p_cn, g_cn);
    cudaGetSymbolAddress(&p_zh, g_z_h);
    cudaGetSymbolAddress(&p_zn2, g_zn2);
    cudaGetSymbolAddress(&p_dest, g_destMap);
    cudaGetSymbolAddress(&p_hist, g_hist);
    cudaGetSymbolAddress(&p_cs, g_classStart);
    cudaGetSymbolAddress(&p_part, g_part);

    int NB = (M + HB - 1) / HB;
    hist_k<<<NB, HB>>>(cy, M, (int*)p_hist);
    scan_k<<<1, 512>>>((int*)p_hist, NB, (int*)p_cs);
    scatter_k<<<NB, HB>>>(cy, M, (const int*)p_hist, (const int*)p_cs, (int*)p_dest);

    int nbQ = N / 128, nbC = M / 128;
    cudaFuncSetAttribute(encode_mma_k, cudaFuncAttributeMaxDynamicSharedMemorySize, E_TOTAL);
    encode_mma_k<<<nbQ + nbC, 256, E_TOTAL>>>(x, cx, nbQ, (const int*)p_dest, W, b,
        (__half*)p_zh, (float*)p_zn2, (__half*)p_ch, (float*)p_cn);

    cudaFuncSetAttribute(nca_mma_k, cudaFuncAttributeMaxDynamicSharedMemorySize, SM_TOTAL);
    dim3 g(N / 128, NSPLIT);
    nca_mma_k<<<g, 256, SM_TOTAL>>>(
        (const __half*)p_zh, (const float*)p_zn2,
        (const __half*)p_ch, (const float*)p_cn,
        (const int*)p_cs, (float*)p_part, M, N);

    finalize_k<<<(N + 255) / 256, 256>>>((const float*)p_part, out, N);
}

// round 13
// speedup vs baseline: 1.7737x; 1.0054x over previous
#include <cuda_runtime.h>
#include <cuda_fp16.h>
#include <math.h>
#include <stdint.h>

#define FULLMASK 0xffffffffu
#define NCLS 10
#define MAXM 131072
#define MAXN 2048
#define NSPLIT 18
#define HB 256

// store z * log2(e) so ex2(-sqrt(sq')) = exp(-dist); norms * log2(e)^2
#define ZSCL 1.4426950408889634f
#define NSCL 2.081368981144074f

// ---------------- scratch (static device globals; no allocation) ------------
__device__ __half g_zc_h[MAXM * 128];
__device__ float  g_cn[MAXM];
__device__ __half g_z_h[MAXN * 128];
__device__ float  g_zn2[MAXN];
__device__ __align__(16) __half g_Wh[128 * 128];   // pre-swizzled fp16 W tile
__device__ int    g_destMap[MAXM];
__device__ int    g_hist[(MAXM / HB) * NCLS];
__device__ int    g_classStart[NCLS + 1];
__device__ float  g_part[NSPLIT * MAXN * NCLS];

// ---------------- PTX helpers (baseline sm_80+ only) -------------------------
__device__ __forceinline__ uint32_t smem_u32(const void* p) {
    uint32_t a;
    asm("{ .reg .u64 t; cvta.to.shared.u64 t, %1; cvt.u32.u64 %0, t; }" : "=r"(a) : "l"(p));
    return a;
}

__device__ __forceinline__ uint32_t h2u(__half2 h) {
    union { __half2 h; uint32_t u; } cvt;
    cvt.h = h;
    return cvt.u;
}

__device__ __forceinline__ float2 u2f2(uint32_t u) {
    union { __half2 h; uint32_t u; } cvt;
    cvt.u = u;
    return __half22float2(cvt.h);
}

#define CP16(saddr, gptr) \
    asm volatile("cp.async.cg.shared.global [%0], [%1], 16;" :: "r"(saddr), "l"(gptr))
#define CP_COMMIT() asm volatile("cp.async.commit_group;" ::: "memory")
#define CP_WAIT(n)  asm volatile("cp.async.wait_group %0;" :: "n"(n) : "memory")

#define LDSM4(r, addr) \
    asm volatile("ldmatrix.sync.aligned.m8n8.x4.shared.b16 {%0,%1,%2,%3}, [%4];" \
        : "=r"((r)[0]), "=r"((r)[1]), "=r"((r)[2]), "=r"((r)[3]) : "r"(addr))

// fp16-accumulate mma: D,C are 2 packed b32 regs (4 halves)
#define MMA_F16ACC(d, a, b0v, b1v) \
    asm volatile("mma.sync.aligned.m16n8k16.row.col.f16.f16.f16.f16 " \
        "{%0,%1},{%2,%3,%4,%5},{%6,%7},{%0,%1};" \
        : "+r"((d)[0]), "+r"((d)[1]) \
        : "r"((a)[0]), "r"((a)[1]), "r"((a)[2]), "r"((a)[3]), "r"(b0v), "r"(b1v))

// ---------------- counting sort by class (256-thread blocks) -----------------
__global__ __launch_bounds__(HB)
void hist_k(const int* __restrict__ y, int M, int* __restrict__ hist) {
    __shared__ int wc[HB / 32][NCLS];
    int tid = threadIdx.x, w = tid >> 5;
    int i = blockIdx.x * HB + tid;
    int c = (i < M) ? y[i] : -1;
#pragma unroll
    for (int cls = 0; cls < NCLS; ++cls) {
        unsigned b = __ballot_sync(FULLMASK, c == cls);
        if ((tid & 31) == 0) wc[w][cls] = __popc(b);
    }
    __syncthreads();
    if (tid < NCLS) {
        int s = 0;
#pragma unroll
        for (int ww = 0; ww < HB / 32; ++ww) s += wc[ww][tid];
        hist[blockIdx.x * NCLS + tid] = s;
    }
}

// parallel per-class exclusive scan over NB block-histograms (512 threads)
__global__ __launch_bounds__(512)
void scan_k(int* hist, int NB, int* classStart) {
    __shared__ int buf[512];
    __shared__ int carry[NCLS];
    int tid = threadIdx.x;
    if (tid < NCLS) carry[tid] = 0;
    __syncthreads();
    for (int c = 0; c < NCLS; ++c) {
        for (int b0 = 0; b0 < NB; b0 += 512) {
            int idx = b0 + tid;
            int v = (idx < NB) ? hist[idx * NCLS + c] : 0;
            buf[tid] = v;
            __syncthreads();
#pragma unroll
            for (int off = 1; off < 512; off <<= 1) {
                int t = (tid >= off) ? buf[tid - off] : 0;
                __syncthreads();
                buf[tid] += t;
                __syncthreads();
            }
            if (idx < NB) hist[idx * NCLS + c] = carry[c] + buf[tid] - v;
            __syncthreads();
            if (tid == 0) carry[c] += buf[511];
            __syncthreads();
        }
    }
    if (tid == 0) {
        int a = 0;
        for (int i = 0; i < NCLS; ++i) { classStart[i] = a; a += carry[i]; }
        classStart[NCLS] = a;
    }
}

__global__ __launch_bounds__(HB)
void scatter_k(const int* __restrict__ y, int M,
               const int* __restrict__ hist,
               const int* __restrict__ classStart,
               int* __restrict__ dest) {
    __shared__ int wc[HB / 32][NCLS];
    int tid = threadIdx.x, w = tid >> 5, lane = tid & 31;
    int i = blockIdx.x * HB + tid;
    int c = (i < M) ? y[i] : -1;
    unsigned mymask = 0;
#pragma unroll
    for (int cls = 0; cls < NCLS; ++cls) {
        unsigned b = __ballot_sync(FULLMASK, c == cls);
        if (lane == 0) wc[w][cls] = __popc(b);
        if (c == cls) mymask = b;
    }
    __syncthreads();
    if (tid < NCLS) {
        int run = 0;
#pragma unroll
        for (int ww = 0; ww < HB / 32; ++ww) {
            int t = wc[ww][tid];
            wc[ww][tid] = run;
            run += t;
        }
    }
    __syncthreads();
    if (i < M) {
        int rank = __popc(mymask & ((1u << lane) - 1u));
        dest[i] = classStart[c] + hist[blockIdx.x * NCLS + c] + wc[w][c] + rank;
    }
}

// ---------------- W pre-convert: fp32 -> pre-swizzled fp16 tile --------------
__global__ __launch_bounds__(256)
void wconv_k(const float* __restrict__ W, __half* __restrict__ Wh) {
    int i4 = blockIdx.x * 256 + threadIdx.x;      // 0..4095 float4 index
    int row = i4 >> 5, c4 = i4 & 31;
    float4 v = ((const float4*)W)[i4];
    uint32_t h0 = h2u(__floats2half2_rn(v.x, v.y));
    uint32_t h1 = h2u(__floats2half2_rn(v.z, v.w));
    uint32_t off = row * 256 + ((((uint32_t)(c4 >> 1)) ^ (row & 7)) << 4) + (c4 & 1) * 8;
    *(uint2*)((char*)Wh + off) = make_uint2(h0, h1);
}

// ---------------- HMMA encoder: 64 rows x 128 dims per CTA -------------------
#define E_XH    0        // 64x256B fp16 swizzled (reused as zout, linear)
#define E_WH    16384    // 128x256B fp16 swizzled (cp.async from g_Wh)
#define E_BIAS  49152    // 128 f32
#define E_NRM   49664    // 64 f32
#define E_DST   49920    // 64 int
#define E_TOTAL 50176

__global__ __launch_bounds__(256, 3)
void encode_mma_k(const float* __restrict__ Xq, const float* __restrict__ Xc, int nbQ,
                  const int* __restrict__ destMap,
                  const __half* __restrict__ Wh, const float* __restrict__ bias,
                  __half* __restrict__ zqH, float* __restrict__ zqN,
                  __half* __restrict__ zcH, float* __restrict__ zcN) {
    extern __shared__ char smc[];
    char* sm = smc;
    const uint32_t sb = smem_u32(sm);
    const int tid = threadIdx.x;
    const int w = tid >> 5, lane = tid & 31;
    const int warpM = w & 1, warpN = w >> 1;     // 2x4 grid, 32x32 warp tile
    const int q2 = (lane & 3) * 2;
    const int bid = blockIdx.x;
    const bool isQ = bid < nbQ;
    const int rowBase = (isQ ? bid : bid - nbQ) * 64;
    const float* src = isQ ? (Xq + (size_t)rowBase * 128) : (Xc + (size_t)rowBase * 128);
    __half* outH = isQ ? zqH : zcH;
    float* outN = isQ ? zqN : zcN;

    // async-copy pre-swizzled W (32KB, linear)
#pragma unroll
    for (int t = 0; t < 8; ++t) {
        int idx = tid + t * 256;
        CP16(sb + E_WH + idx * 16, (const uint4*)Wh + idx);
    }
    CP_COMMIT();

    // load + convert X tile (64 rows) into swizzled fp16 smem
#pragma unroll
    for (int t = 0; t < 8; ++t) {
        int i4 = tid + t * 256;                  // float4 index, 0..2047
        int row = i4 >> 5, c4 = i4 & 31;
        float4 v = ((const float4*)src)[i4];
        uint32_t h0 = h2u(__floats2half2_rn(v.x, v.y));
        uint32_t h1 = h2u(__floats2half2_rn(v.z, v.w));
        uint32_t off = row * 256 + ((((uint32_t)(c4 >> 1)) ^ (row & 7)) << 4) + (c4 & 1) * 8;
        *(uint2*)(sm + E_XH + off) = make_uint2(h0, h1);
    }
    if (tid < 128) ((float*)(sm + E_BIAS))[tid] = bias[tid];
    if (tid < 64) {
        ((float*)(sm + E_NRM))[tid] = 0.f;
        ((int*)(sm + E_DST))[tid] = isQ ? (rowBase + tid) : destMap[rowBase + tid];
    }
    CP_WAIT(0);
    __syncthreads();

    uint32_t aoff[2], asw[2];
#pragma unroll
    for (int mi = 0; mi < 2; ++mi) {
        int row = warpM * 32 + mi * 16 + (lane & 15);
        aoff[mi] = row * 256;
        asw[mi] = row & 7;
    }
    const uint32_t achb = lane >> 4;
    uint32_t boff[2], bsw[2];
#pragma unroll
    for (int g = 0; g < 2; ++g) {
        int row = warpN * 32 + g * 16 + (lane & 7) + ((lane >> 4) << 3);
        boff[g] = row * 256;
        bsw[g] = row & 7;
    }
    const uint32_t bchb = (lane >> 3) & 1;

    uint32_t acch[2][4][2];
#pragma unroll
    for (int mi = 0; mi < 2; ++mi)
#pragma unroll
        for (int ni = 0; ni < 4; ++ni) { acch[mi][ni][0] = 0u; acch[mi][ni][1] = 0u; }

#pragma unroll
    for (int k8 = 0; k8 < 8; ++k8) {
        uint32_t af[2][4], bf[2][4];
        uint32_t ca = 2 * k8 + achb, cbk = 2 * k8 + bchb;
#pragma unroll
        for (int mi = 0; mi < 2; ++mi)
            LDSM4(af[mi], sb + E_XH + aoff[mi] + ((ca ^ asw[mi]) << 4));
#pragma unroll
        for (int g = 0; g < 2; ++g)
            LDSM4(bf[g], sb + E_WH + boff[g] + ((cbk ^ bsw[g]) << 4));
#pragma unroll
        for (int mi = 0; mi < 2; ++mi)
#pragma unroll
            for (int ni = 0; ni < 4; ++ni) {
                int g = ni >> 1, p = (ni & 1) * 2;
                MMA_F16ACC(acch[mi][ni], af[mi], bf[g][p], bf[g][p + 1]);
            }
    }
    __syncthreads();   // all ldmatrix reads done; E_XH reusable as zout

    float bcol[4][2];
#pragma unroll
    for (int ni = 0; ni < 4; ++ni) {
        bcol[ni][0] = ((const float*)(sm + E_BIAS))[warpN * 32 + ni * 8 + q2];
        bcol[ni][1] = ((const float*)(sm + E_BIAS))[warpN * 32 + ni * 8 + q2 + 1];
    }
#pragma unroll
    for (int mi = 0; mi < 2; ++mi)
#pragma unroll
        for (int h = 0; h < 2; ++h) {
            int row = warpM * 32 + mi * 16 + (lane >> 2) + h * 8;
            float s = 0.f;
#pragma unroll
            for (int ni = 0; ni < 4; ++ni) {
                float2 pr = u2f2(acch[mi][ni][h]);
                float v0 = pr.x + bcol[ni][0];
                float v1 = pr.y + bcol[ni][1];
                s += v0 * v0 + v1 * v1;
                __half2 hv = __floats2half2_rn(v0 * ZSCL, v1 * ZSCL);
                *(uint32_t*)(sm + E_XH + row * 256 + (warpN * 32 + ni * 8 + q2) * 2) = h2u(hv);
            }
            s += __shfl_xor_sync(FULLMASK, s, 1);
            s += __shfl_xor_sync(FULLMASK, s, 2);
            if ((lane & 3) == 0)
                atomicAdd((float*)(sm + E_NRM) + row, s);
        }
    __syncthreads();

    // coalesced writeback: warp w handles rows w*8 .. w*8+7
#pragma unroll
    for (int rr = 0; rr < 8; ++rr) {
        int row = w * 8 + rr;
        int d = ((const int*)(sm + E_DST))[row];
        uint2 v = *(uint2*)(sm + E_XH + row * 256 + lane * 8);
        ((uint2*)(outH + (size_t)d * 128))[lane] = v;
        if (lane == 0) outN[d] = ((const float*)(sm + E_NRM))[row] * NSCL;
    }
}

// ---------------- main: fp16-acc HMMA, per-pair sync + per-pair prefetch -----
#define SM_ZH    0
#define SM_B     32768     // 2 stages x 32768
#define SM_CN    98304     // 2 x 512
#define SM_SACC  99328     // 128*10 floats
#define SM_TOTAL 104448

#define BAR_PAIR(pid) asm volatile("bar.sync %0, 64;" :: "r"(1 + (pid)) : "memory")

// CTA-wide copy of one 128x128 fp16 tile (32KB) into swizzled smem
__device__ __forceinline__ void issue_tile(uint32_t sbase, const uint4* __restrict__ g,
                                           int tid) {
#pragma unroll
    for (int t = 0; t < 8; ++t) {
        int idx = tid + t * 256;            // 0..2047, = row*16 + chunk
        int row = idx >> 4, c = idx & 15;
        uint32_t saddr = sbase + row * 256 + ((c ^ (row & 7)) << 4);
        CP16(saddr, g + idx);
    }
}

// pair-partitioned copy: pair p loads rows [p*32, p*32+32) (8KB, 64 threads)
__device__ __forceinline__ void issue_pair_tile(uint32_t sbase, const uint4* __restrict__ g,
                                                int pid, int tid64) {
#pragma unroll
    for (int t = 0; t < 8; ++t) {
        int idx = pid * 512 + tid64 + t * 64;   // uint4 index = row*16 + chunk
        int row = idx >> 4, c = idx & 15;
        uint32_t saddr = sbase + row * 256 + ((c ^ (row & 7)) << 4);
        CP16(saddr, g + idx);
    }
}

__global__ __launch_bounds__(256, 2)
void nca_mma_k(const __half* __restrict__ zh_g, const float* __restrict__ zn2,
               const __half* __restrict__ ch_g, const float* __restrict__ cn_g,
               const int* __restrict__ classStart,
               float* __restrict__ part, int M, int N) {
    extern __shared__ char smc[];
    char* sm = smc;
    const uint32_t sb = smem_u32(sm);
    const int tid = threadIdx.x;
    const int w = tid >> 5, lane = tid & 31;
    const int warpM = w & 1, warpN = w >> 1;   // 2 x 4 warp grid; 64 x 32 per warp
    const int pid = tid >> 6;                   // pair id == warpN
    const int tid64 = tid & 63;
    const int q2 = (lane & 3) * 2;
    const int tile = blockIdx.x, split = blockIdx.y;
    const int chunksTotal = M >> 7;
    const int cpb = (chunksTotal + NSPLIT - 1) / NSPLIT;
    const int cLo = split * cpb;
    const int cHi = min(cLo + cpb, chunksTotal);
    const int nch = cHi - cLo;

    for (int i = tid; i < 128 * NCLS; i += 256) ((float*)(sm + SM_SACC))[i] = 0.f;

    int cs[NCLS + 1];
#pragma unroll
    for (int k = 0; k <= NCLS; ++k) cs[k] = classStart[k];

    float znr[4][2];
#pragma unroll
    for (int mi = 0; mi < 4; ++mi) {
        int r = tile * 128 + warpM * 64 + mi * 16 + (lane >> 2);
        znr[mi][0] = zn2[r];
        znr[mi][1] = zn2[r + 8];
    }

    // prologue: z CTA-wide; stage0/stage1 + cn partitioned per pair
    issue_tile(sb + SM_ZH, (const uint4*)zh_g + (size_t)tile * 2048, tid);
    issue_pair_tile(sb + SM_B, (const uint4*)ch_g + (size_t)cLo * 2048, pid, tid64);
    if (tid64 < 8) CP16(sb + SM_CN + pid * 128 + tid64 * 16,
                        (const float*)cn_g + (size_t)cLo * 128 + pid * 32 + tid64 * 4);
    CP_COMMIT();
    if (nch > 1) {
        issue_pair_tile(sb + SM_B + 32768, (const uint4*)ch_g + (size_t)(cLo + 1) * 2048,
                        pid, tid64);
        if (tid64 < 8) CP16(sb + SM_CN + 512 + pid * 128 + tid64 * 16,
                            (const float*)cn_g + (size_t)(cLo + 1) * 128 + pid * 32 + tid64 * 4);
    }
    CP_COMMIT();

    // ldmatrix address precompute
    uint32_t aoff[4], asw[4];
#pragma unroll
    for (int mi = 0; mi < 4; ++mi) {
        int row = warpM * 64 + mi * 16 + (lane & 15);
        aoff[mi] = row * 256;
        asw[mi] = row & 7;
    }
    const uint32_t achb = lane >> 4;
    uint32_t boff[2], bsw[2];
#pragma unroll
    for (int g = 0; g < 2; ++g) {
        int row = warpN * 32 + g * 16 + (lane & 7) + ((lane >> 4) << 3);
        boff[g] = row * 256;
        bsw[g] = row & 7;
    }
    const uint32_t bchb = (lane >> 3) & 1;

    CP_WAIT(1);
    __syncthreads();                 // z + stage0 + sacc zero visible CTA-wide

    for (int i = 0; i < nch; ++i) {
        if (i > 0) {
            CP_WAIT(1);
            BAR_PAIR(pid);           // pair's stage (i&1) slice visible
        }

        const int cb = i & 1;
        const uint32_t bbase = sb + SM_B + cb * 32768;
        const uint32_t abase = sb + SM_ZH;

        uint32_t acch[4][4][2];
#pragma unroll
        for (int mi = 0; mi < 4; ++mi)
#pragma unroll
            for (int ni = 0; ni < 4; ++ni) { acch[mi][ni][0] = 0u; acch[mi][ni][1] = 0u; }

#pragma unroll
        for (int k8 = 0; k8 < 8; ++k8) {
            uint32_t af[4][4], bf[2][4];
            uint32_t ca = 2 * k8 + achb, cbk = 2 * k8 + bchb;
#pragma unroll
            for (int mi = 0; mi < 4; ++mi)
                LDSM4(af[mi], abase + aoff[mi] + ((ca ^ asw[mi]) << 4));
#pragma unroll
            for (int g = 0; g < 2; ++g)
                LDSM4(bf[g], bbase + boff[g] + ((cbk ^ bsw[g]) << 4));
#pragma unroll
            for (int mi = 0; mi < 4; ++mi)
#pragma unroll
                for (int ni = 0; ni < 4; ++ni) {
                    int g = ni >> 1, p = (ni & 1) * 2;
                    MMA_F16ACC(acch[mi][ni], af[mi], bf[g][p], bf[g][p + 1]);
                }
        }

        // pull candidate norms into registers BEFORE freeing the stage
        float cnv[4][2];
#pragma unroll
        for (int ni = 0; ni < 4; ++ni) {
            cnv[ni][0] = *(const float*)(sm + SM_CN + cb * 512 + (warpN * 32 + ni * 8 + q2) * 4);
            cnv[ni][1] = *(const float*)(sm + SM_CN + cb * 512 + (warpN * 32 + ni * 8 + q2 + 1) * 4);
        }

        BAR_PAIR(pid);               // pair's reads of its stage-cb slice done

        // prefetch chunk i+2 into pair's slice of stage cb; overlaps epilogue
        if (i + 2 < nch) {
            issue_pair_tile(sb + SM_B + cb * 32768,
                            (const uint4*)ch_g + (size_t)(cLo + i + 2) * 2048, pid, tid64);
            if (tid64 < 8) CP16(sb + SM_CN + cb * 512 + pid * 128 + tid64 * 16,
                                (const float*)cn_g + (size_t)(cLo + i + 2) * 128 +
                                pid * 32 + tid64 * 4);
        }
        CP_COMMIT();

        // unpack + dist -> exp(-dist)
        float acc[4][4][4];
#pragma unroll
        for (int mi = 0; mi < 4; ++mi)
#pragma unroll
            for (int ni = 0; ni < 4; ++ni) {
                float2 lo = u2f2(acch[mi][ni][0]);
                float2 hi = u2f2(acch[mi][ni][1]);
                acc[mi][ni][0] = lo.x; acc[mi][ni][1] = lo.y;
                acc[mi][ni][2] = hi.x; acc[mi][ni][3] = hi.y;
            }
#pragma unroll
        for (int ni = 0; ni < 4; ++ni)
#pragma unroll
            for (int mi = 0; mi < 4; ++mi)
#pragma unroll
                for (int k = 0; k < 4; ++k) {
                    float base = znr[mi][k >> 1] + cnv[ni][k & 1];
                    float sq = fmaf(-2.f, acc[mi][ni][k], base);
                    float dd;
                    asm("sqrt.approx.f32 %0, %1;" : "=f"(dd) : "f"(sq));
                    float nd = -dd;
                    asm("ex2.approx.f32 %0, %1;" : "=f"(acc[mi][ni][k]) : "f"(nd));
                }

        // class-segmented accumulation (candidates sorted by class)
        const int wb = (cLo + i) * 128 + warpN * 32;
        int c0 = 0;
        while (c0 < NCLS - 1 && cs[c0 + 1] <= wb) ++c0;
        int c1 = c0;
        while (c1 < NCLS - 1 && cs[c1 + 1] < wb + 32) ++c1;
        if (c0 == c1) {
#pragma unroll
            for (int mi = 0; mi < 4; ++mi)
#pragma unroll
                for (int h = 0; h < 2; ++h) {
                    float s = 0.f;
#pragma unroll
                    for (int ni = 0; ni < 4; ++ni)
#pragma unroll
                        for (int j = 0; j < 2; ++j) s += acc[mi][ni][h * 2 + j];
                    s += __shfl_xor_sync(FULLMASK, s, 1);
                    s += __shfl_xor_sync(FULLMASK, s, 2);
                    if ((lane & 3) == 0) {
                        int r = warpM * 64 + mi * 16 + (lane >> 2) + h * 8;
                        atomicAdd((float*)(sm + SM_SACC) + r * NCLS + c0, s);
                    }
                }
        } else {
            for (int c = c0; c <= c1; ++c) {
                int lo = max(cs[c] - wb, 0), hi = min(cs[c + 1] - wb, 32);
#pragma unroll
                for (int mi = 0; mi < 4; ++mi)
#pragma unroll
                    for (int h = 0; h < 2; ++h) {
                        float s = 0.f;
#pragma unroll
                        for (int ni = 0; ni < 4; ++ni)
#pragma unroll
                            for (int j = 0; j < 2; ++j) {
                                int nl = ni * 8 + q2 + j;
                                s += (nl >= lo && nl < hi) ? acc[mi][ni][h * 2 + j] : 0.f;
                            }
                        s += __shfl_xor_sync(FULLMASK, s, 1);
                        s += __shfl_xor_sync(FULLMASK, s, 2);
                        if ((lane & 3) == 0) {
                            int r = warpM * 64 + mi * 16 + (lane >> 2) + h * 8;
                            atomicAdd((float*)(sm + SM_SACC) + r * NCLS + c, s);
                        }
                    }
            }
        }
    }

    __syncthreads();                 // all pairs' atomicAdds complete
    if (tid < 128) {
        int qg = tile * 128 + tid;
#pragma unroll
        for (int c = 0; c < NCLS; ++c)
            part[((size_t)split * N + qg) * NCLS + c] =
                ((float*)(sm + SM_SACC))[tid * NCLS + c];
    }
}

// ---------------- finalize: combine splits, normalize, log ------------------
__global__ void finalize_k(const float* __restrict__ part, float* __restrict__ out, int N) {
    int n = blockIdx.x * blockDim.x + threadIdx.x;
    if (n >= N) return;
    float t[NCLS];
#pragma unroll
    for (int c = 0; c < NCLS; ++c) t[c] = 0.f;
    for (int s = 0; s < NSPLIT; ++s)
#pragma unroll
        for (int c = 0; c < NCLS; ++c) t[c] += part[((size_t)s * N + n) * NCLS + c];
    float tot = 0.f;
#pragma unroll
    for (int c = 0; c < NCLS; ++c) tot += t[c];
    float inv = 1.f / tot;
#pragma unroll
    for (int c = 0; c < NCLS; ++c) out[n * NCLS + c] = logf(fmaf(t[c], inv, 1e-7f));
}

// ---------------- launch ----------------------------------------------------
extern "C" void kernel_launch(void* const* d_in, const int* in_sizes, int n_in,
                              void* d_out, int out_size) {
    const float* x  = (const float*)d_in[0];
    const float* cx = (const float*)d_in[1];
    const int*   cy = (const int*)d_in[2];
    const float* W  = (const float*)d_in[3];
    const float* b  = (const float*)d_in[4];
    int N = in_sizes[0] / 128;
    int M = in_sizes[2];
    float* out = (float*)d_out;

    void *p_ch, *p_cn, *p_zh, *p_zn2, *p_wh, *p_dest, *p_hist, *p_cs, *p_part;
    cudaGetSymbolAddress(&p_ch, g_zc_h);
    cudaGetSymbolAddress(&p_cn, g_cn);
    cudaGetSymbolAddress(&p_zh, g_z_h);
    cudaGetSymbolAddress(&p_zn2, g_zn2);
    cudaGetSymbolAddress(&p_wh, g_Wh);
    cudaGetSymbolAddress(&p_dest, g_destMap);
    cudaGetSymbolAddress(&p_hist, g_hist);
    cudaGetSymbolAddress(&p_cs, g_classStart);
    cudaGetSymbolAddress(&p_part, g_part);

    wconv_k<<<16, 256>>>(W, (__half*)p_wh);

    int NB = (M + HB - 1) / HB;
    hist_k<<<NB, HB>>>(cy, M, (int*)p_hist);
    scan_k<<<1, 512>>>((int*)p_hist, NB, (int*)p_cs);
    scatter_k<<<NB, HB>>>(cy, M, (const int*)p_hist, (const int*)p_cs, (int*)p_dest);

    int nbQ = N / 64, nbC = M / 64;
    cudaFuncSetAttribute(encode_mma_k, cudaFuncAttributeMaxDynamicSharedMemorySize, E_TOTAL);
    encode_mma_k<<<nbQ + nbC, 256, E_TOTAL>>>(x, cx, nbQ, (const int*)p_dest,
        (const __half*)p_wh, b,
        (__half*)p_zh, (float*)p_zn2, (__half*)p_ch, (float*)p_cn);

    cudaFuncSetAttribute(nca_mma_k, cudaFuncAttributeMaxDynamicSharedMemorySize, SM_TOTAL);
    dim3 g(N / 128, NSPLIT);
    nca_mma_k<<<g, 256, SM_TOTAL>>>(
        (const __half*)p_zh, (const float*)p_zn2,
        (const __half*)p_ch, (const float*)p_cn,
        (const int*)p_cs, (float*)p_part, M, N);

    finalize_k<<<(N + 255) / 256, 256>>>((const float*)p_part, out, N);
}

// round 14
// speedup vs baseline: 1.7947x; 1.0118x over previous
#include <cuda_runtime.h>
#include <cuda_fp16.h>
#include <math.h>
#include <stdint.h>

#define FULLMASK 0xffffffffu
#define NCLS 10
#define MAXM 131072
#define MAXN 2048
#define NSPLIT 18
#define HB 256

// store z * log2(e) so ex2(-sqrt(sq')) = exp(-dist); norms * log2(e)^2
#define ZSCL 1.4426950408889634f
#define NSCL 2.081368981144074f

// ---------------- scratch (static device globals; no allocation) ------------
__device__ __half g_zc_h[MAXM * 128];
__device__ float  g_cn[MAXM];
__device__ __half g_z_h[MAXN * 128];
__device__ float  g_zn2[MAXN];
__device__ __align__(16) __half g_Wh[128 * 128];   // pre-swizzled fp16 W tile
__device__ int    g_destMap[MAXM];
__device__ int    g_hist[(MAXM / HB) * NCLS];
__device__ int    g_classStart[NCLS + 1];
__device__ float  g_part[NSPLIT * MAXN * NCLS];

// ---------------- PTX helpers (baseline sm_80+ only) -------------------------
__device__ __forceinline__ uint32_t smem_u32(const void* p) {
    uint32_t a;
    asm("{ .reg .u64 t; cvta.to.shared.u64 t, %1; cvt.u32.u64 %0, t; }" : "=r"(a) : "l"(p));
    return a;
}

__device__ __forceinline__ uint32_t h2u(__half2 h) {
    union { __half2 h; uint32_t u; } cvt;
    cvt.h = h;
    return cvt.u;
}

__device__ __forceinline__ float2 u2f2(uint32_t u) {
    union { __half2 h; uint32_t u; } cvt;
    cvt.u = u;
    return __half22float2(cvt.h);
}

#define CP16(saddr, gptr) \
    asm volatile("cp.async.cg.shared.global [%0], [%1], 16;" :: "r"(saddr), "l"(gptr))
#define CP_COMMIT() asm volatile("cp.async.commit_group;" ::: "memory")
#define CP_WAIT(n)  asm volatile("cp.async.wait_group %0;" :: "n"(n) : "memory")

#define LDSM4(r, addr) \
    asm volatile("ldmatrix.sync.aligned.m8n8.x4.shared.b16 {%0,%1,%2,%3}, [%4];" \
        : "=r"((r)[0]), "=r"((r)[1]), "=r"((r)[2]), "=r"((r)[3]) : "r"(addr))

// fp16-accumulate mma: D,C are 2 packed b32 regs (4 halves)
#define MMA_F16ACC(d, a, b0v, b1v) \
    asm volatile("mma.sync.aligned.m16n8k16.row.col.f16.f16.f16.f16 " \
        "{%0,%1},{%2,%3,%4,%5},{%6,%7},{%0,%1};" \
        : "+r"((d)[0]), "+r"((d)[1]) \
        : "r"((a)[0]), "r"((a)[1]), "r"((a)[2]), "r"((a)[3]), "r"(b0v), "r"(b1v))

// ---------------- fused histogram + W convert --------------------------------
// blocks [0, NB): per-block class histogram of y
// blocks [NB, NB+16): convert fp32 W into pre-swizzled fp16 g_Wh
__global__ __launch_bounds__(HB)
void hist_k(const int* __restrict__ y, int M, int* __restrict__ hist, int NB,
            const float* __restrict__ W, __half* __restrict__ Wh) {
    if ((int)blockIdx.x >= NB) {
        int i4 = (blockIdx.x - NB) * 256 + threadIdx.x;   // 0..4095 float4 index
        int row = i4 >> 5, c4 = i4 & 31;
        float4 v = ((const float4*)W)[i4];
        uint32_t h0 = h2u(__floats2half2_rn(v.x, v.y));
        uint32_t h1 = h2u(__floats2half2_rn(v.z, v.w));
        uint32_t off = row * 256 + ((((uint32_t)(c4 >> 1)) ^ (row & 7)) << 4) + (c4 & 1) * 8;
        *(uint2*)((char*)Wh + off) = make_uint2(h0, h1);
        return;
    }
    __shared__ int wc[HB / 32][NCLS];
    int tid = threadIdx.x, w = tid >> 5;
    int i = blockIdx.x * HB + tid;
    int c = (i < M) ? y[i] : -1;
#pragma unroll
    for (int cls = 0; cls < NCLS; ++cls) {
        unsigned b = __ballot_sync(FULLMASK, c == cls);
        if ((tid & 31) == 0) wc[w][cls] = __popc(b);
    }
    __syncthreads();
    if (tid < NCLS) {
        int s = 0;
#pragma unroll
        for (int ww = 0; ww < HB / 32; ++ww) s += wc[ww][tid];
        hist[blockIdx.x * NCLS + tid] = s;
    }
}

// ---------------- scan: one warp per class, shuffle-based --------------------
__global__ __launch_bounds__(320)
void scan_k(int* hist, int NB, int* classStart) {
    __shared__ int tot[NCLS];
    int w = threadIdx.x >> 5, lane = threadIdx.x & 31;
    if (w < NCLS) {
        int c = w;
        int carry = 0;
        for (int b0 = 0; b0 < NB; b0 += 512) {
            int vals[16];
            int s = 0;
            int base = b0 + lane * 16;
#pragma unroll
            for (int t = 0; t < 16; ++t) {
                int idx = base + t;
                int v = (idx < NB) ? hist[idx * NCLS + c] : 0;
                vals[t] = s;               // within-lane exclusive prefix
                s += v;
            }
            int run = s;
#pragma unroll
            for (int off = 1; off < 32; off <<= 1) {
                int t = __shfl_up_sync(FULLMASK, run, off);
                if (lane >= off) run += t;
            }
            int excl = carry + run - s;    // exclusive prefix for this lane's base
#pragma unroll
            for (int t = 0; t < 16; ++t) {
                int idx = base + t;
                if (idx < NB) hist[idx * NCLS + c] = excl + vals[t];
            }
            carry += __shfl_sync(FULLMASK, run, 31);
        }
        if (lane == 0) tot[c] = carry;
    }
    __syncthreads();
    if (threadIdx.x == 0) {
        int a = 0;
        for (int i = 0; i < NCLS; ++i) { classStart[i] = a; a += tot[i]; }
        classStart[NCLS] = a;
    }
}

__global__ __launch_bounds__(HB)
void scatter_k(const int* __restrict__ y, int M,
               const int* __restrict__ hist,
               const int* __restrict__ classStart,
               int* __restrict__ dest) {
    __shared__ int wc[HB / 32][NCLS];
    int tid = threadIdx.x, w = tid >> 5, lane = tid & 31;
    int i = blockIdx.x * HB + tid;
    int c = (i < M) ? y[i] : -1;
    unsigned mymask = 0;
#pragma unroll
    for (int cls = 0; cls < NCLS; ++cls) {
        unsigned b = __ballot_sync(FULLMASK, c == cls);
        if (lane == 0) wc[w][cls] = __popc(b);
        if (c == cls) mymask = b;
    }
    __syncthreads();
    if (tid < NCLS) {
        int run = 0;
#pragma unroll
        for (int ww = 0; ww < HB / 32; ++ww) {
            int t = wc[ww][tid];
            wc[ww][tid] = run;
            run += t;
        }
    }
    __syncthreads();
    if (i < M) {
        int rank = __popc(mymask & ((1u << lane) - 1u));
        dest[i] = classStart[c] + hist[blockIdx.x * NCLS + c] + wc[w][c] + rank;
    }
}

// ---------------- HMMA encoder: 64 rows x 128 dims per CTA -------------------
#define E_XH    0        // 64x256B fp16 swizzled (reused as zout, linear)
#define E_WH    16384    // 128x256B fp16 swizzled (cp.async from g_Wh)
#define E_BIAS  49152    // 128 f32
#define E_NRM   49664    // 64 f32
#define E_DST   49920    // 64 int
#define E_TOTAL 50176

__global__ __launch_bounds__(256, 3)
void encode_mma_k(const float* __restrict__ Xq, const float* __restrict__ Xc, int nbQ,
                  const int* __restrict__ destMap,
                  const __half* __restrict__ Wh, const float* __restrict__ bias,
                  __half* __restrict__ zqH, float* __restrict__ zqN,
                  __half* __restrict__ zcH, float* __restrict__ zcN) {
    extern __shared__ char smc[];
    char* sm = smc;
    const uint32_t sb = smem_u32(sm);
    const int tid = threadIdx.x;
    const int w = tid >> 5, lane = tid & 31;
    const int warpM = w & 1, warpN = w >> 1;     // 2x4 grid, 32x32 warp tile
    const int q2 = (lane & 3) * 2;
    const int bid = blockIdx.x;
    const bool isQ = bid < nbQ;
    const int rowBase = (isQ ? bid : bid - nbQ) * 64;
    const float* src = isQ ? (Xq + (size_t)rowBase * 128) : (Xc + (size_t)rowBase * 128);
    __half* outH = isQ ? zqH : zcH;
    float* outN = isQ ? zqN : zcN;

    // async-copy pre-swizzled W (32KB, linear)
#pragma unroll
    for (int t = 0; t < 8; ++t) {
        int idx = tid + t * 256;
        CP16(sb + E_WH + idx * 16, (const uint4*)Wh + idx);
    }
    CP_COMMIT();

    // load + convert X tile (64 rows) into swizzled fp16 smem
#pragma unroll
    for (int t = 0; t < 8; ++t) {
        int i4 = tid + t * 256;                  // float4 index, 0..2047
        int row = i4 >> 5, c4 = i4 & 31;
        float4 v = ((const float4*)src)[i4];
        uint32_t h0 = h2u(__floats2half2_rn(v.x, v.y));
        uint32_t h1 = h2u(__floats2half2_rn(v.z, v.w));
        uint32_t off = row * 256 + ((((uint32_t)(c4 >> 1)) ^ (row & 7)) << 4) + (c4 & 1) * 8;
        *(uint2*)(sm + E_XH + off) = make_uint2(h0, h1);
    }
    if (tid < 128) ((float*)(sm + E_BIAS))[tid] = bias[tid];
    if (tid < 64) {
        ((float*)(sm + E_NRM))[tid] = 0.f;
        ((int*)(sm + E_DST))[tid] = isQ ? (rowBase + tid) : destMap[rowBase + tid];
    }
    CP_WAIT(0);
    __syncthreads();

    uint32_t aoff[2], asw[2];
#pragma unroll
    for (int mi = 0; mi < 2; ++mi) {
        int row = warpM * 32 + mi * 16 + (lane & 15);
        aoff[mi] = row * 256;
        asw[mi] = row & 7;
    }
    const uint32_t achb = lane >> 4;
    uint32_t boff[2], bsw[2];
#pragma unroll
    for (int g = 0; g < 2; ++g) {
        int row = warpN * 32 + g * 16 + (lane & 7) + ((lane >> 4) << 3);
        boff[g] = row * 256;
        bsw[g] = row & 7;
    }
    const uint32_t bchb = (lane >> 3) & 1;

    uint32_t acch[2][4][2];
#pragma unroll
    for (int mi = 0; mi < 2; ++mi)
#pragma unroll
        for (int ni = 0; ni < 4; ++ni) { acch[mi][ni][0] = 0u; acch[mi][ni][1] = 0u; }

#pragma unroll
    for (int k8 = 0; k8 < 8; ++k8) {
        uint32_t af[2][4], bf[2][4];
        uint32_t ca = 2 * k8 + achb, cbk = 2 * k8 + bchb;
#pragma unroll
        for (int mi = 0; mi < 2; ++mi)
            LDSM4(af[mi], sb + E_XH + aoff[mi] + ((ca ^ asw[mi]) << 4));
#pragma unroll
        for (int g = 0; g < 2; ++g)
            LDSM4(bf[g], sb + E_WH + boff[g] + ((cbk ^ bsw[g]) << 4));
#pragma unroll
        for (int mi = 0; mi < 2; ++mi)
#pragma unroll
            for (int ni = 0; ni < 4; ++ni) {
                int g = ni >> 1, p = (ni & 1) * 2;
                MMA_F16ACC(acch[mi][ni], af[mi], bf[g][p], bf[g][p + 1]);
            }
    }
    __syncthreads();   // all ldmatrix reads done; E_XH reusable as zout

    float bcol[4][2];
#pragma unroll
    for (int ni = 0; ni < 4; ++ni) {
        bcol[ni][0] = ((const float*)(sm + E_BIAS))[warpN * 32 + ni * 8 + q2];
        bcol[ni][1] = ((const float*)(sm + E_BIAS))[warpN * 32 + ni * 8 + q2 + 1];
    }
#pragma unroll
    for (int mi = 0; mi < 2; ++mi)
#pragma unroll
        for (int h = 0; h < 2; ++h) {
            int row = warpM * 32 + mi * 16 + (lane >> 2) + h * 8;
            float s = 0.f;
#pragma unroll
            for (int ni = 0; ni < 4; ++ni) {
                float2 pr = u2f2(acch[mi][ni][h]);
                float v0 = pr.x + bcol[ni][0];
                float v1 = pr.y + bcol[ni][1];
                s += v0 * v0 + v1 * v1;
                __half2 hv = __floats2half2_rn(v0 * ZSCL, v1 * ZSCL);
                *(uint32_t*)(sm + E_XH + row * 256 + (warpN * 32 + ni * 8 + q2) * 2) = h2u(hv);
            }
            s += __shfl_xor_sync(FULLMASK, s, 1);
            s += __shfl_xor_sync(FULLMASK, s, 2);
            if ((lane & 3) == 0)
                atomicAdd((float*)(sm + E_NRM) + row, s);
        }
    __syncthreads();

    // coalesced writeback: warp w handles rows w*8 .. w*8+7
#pragma unroll
    for (int rr = 0; rr < 8; ++rr) {
        int row = w * 8 + rr;
        int d = ((const int*)(sm + E_DST))[row];
        uint2 v = *(uint2*)(sm + E_XH + row * 256 + lane * 8);
        ((uint2*)(outH + (size_t)d * 128))[lane] = v;
        if (lane == 0) outN[d] = ((const float*)(sm + E_NRM))[row] * NSCL;
    }
}

// ---------------- main: fp16-acc HMMA, per-pair sync + per-pair prefetch -----
#define SM_ZH    0
#define SM_B     32768     // 2 stages x 32768
#define SM_CN    98304     // 2 x 512
#define SM_SACC  99328     // 128*10 floats
#define SM_TOTAL 104448

#define BAR_PAIR(pid) asm volatile("bar.sync %0, 64;" :: "r"(1 + (pid)) : "memory")

// CTA-wide copy of one 128x128 fp16 tile (32KB) into swizzled smem
__device__ __forceinline__ void issue_tile(uint32_t sbase, const uint4* __restrict__ g,
                                           int tid) {
#pragma unroll
    for (int t = 0; t < 8; ++t) {
        int idx = tid + t * 256;            // 0..2047, = row*16 + chunk
        int row = idx >> 4, c = idx & 15;
        uint32_t saddr = sbase + row * 256 + ((c ^ (row & 7)) << 4);
        CP16(saddr, g + idx);
    }
}

// pair-partitioned copy: pair p loads rows [p*32, p*32+32) (8KB, 64 threads)
__device__ __forceinline__ void issue_pair_tile(uint32_t sbase, const uint4* __restrict__ g,
                                                int pid, int tid64) {
#pragma unroll
    for (int t = 0; t < 8; ++t) {
        int idx = pid * 512 + tid64 + t * 64;   // uint4 index = row*16 + chunk
        int row = idx >> 4, c = idx & 15;
        uint32_t saddr = sbase + row * 256 + ((c ^ (row & 7)) << 4);
        CP16(saddr, g + idx);
    }
}

__global__ __launch_bounds__(256, 2)
void nca_mma_k(const __half* __restrict__ zh_g, const float* __restrict__ zn2,
               const __half* __restrict__ ch_g, const float* __restrict__ cn_g,
               const int* __restrict__ classStart,
               float* __restrict__ part, int M, int N) {
    extern __shared__ char smc[];
    char* sm = smc;
    const uint32_t sb = smem_u32(sm);
    const int tid = threadIdx.x;
    const int w = tid >> 5, lane = tid & 31;
    const int warpM = w & 1, warpN = w >> 1;   // 2 x 4 warp grid; 64 x 32 per warp
    const int pid = tid >> 6;                   // pair id == warpN
    const int tid64 = tid & 63;
    const int q2 = (lane & 3) * 2;
    const int tile = blockIdx.x, split = blockIdx.y;
    const int chunksTotal = M >> 7;
    const int cpb = (chunksTotal + NSPLIT - 1) / NSPLIT;
    const int cLo = split * cpb;
    const int cHi = min(cLo + cpb, chunksTotal);
    const int nch = cHi - cLo;

    for (int i = tid; i < 128 * NCLS; i += 256) ((float*)(sm + SM_SACC))[i] = 0.f;

    int cs[NCLS + 1];
#pragma unroll
    for (int k = 0; k <= NCLS; ++k) cs[k] = classStart[k];

    float znr[4][2];
#pragma unroll
    for (int mi = 0; mi < 4; ++mi) {
        int r = tile * 128 + warpM * 64 + mi * 16 + (lane >> 2);
        znr[mi][0] = zn2[r];
        znr[mi][1] = zn2[r + 8];
    }

    // prologue: z CTA-wide; stage0/stage1 + cn partitioned per pair
    issue_tile(sb + SM_ZH, (const uint4*)zh_g + (size_t)tile * 2048, tid);
    issue_pair_tile(sb + SM_B, (const uint4*)ch_g + (size_t)cLo * 2048, pid, tid64);
    if (tid64 < 8) CP16(sb + SM_CN + pid * 128 + tid64 * 16,
                        (const float*)cn_g + (size_t)cLo * 128 + pid * 32 + tid64 * 4);
    CP_COMMIT();
    if (nch > 1) {
        issue_pair_tile(sb + SM_B + 32768, (const uint4*)ch_g + (size_t)(cLo + 1) * 2048,
                        pid, tid64);
        if (tid64 < 8) CP16(sb + SM_CN + 512 + pid * 128 + tid64 * 16,
                            (const float*)cn_g + (size_t)(cLo + 1) * 128 + pid * 32 + tid64 * 4);
    }
    CP_COMMIT();

    // ldmatrix address precompute
    uint32_t aoff[4], asw[4];
#pragma unroll
    for (int mi = 0; mi < 4; ++mi) {
        int row = warpM * 64 + mi * 16 + (lane & 15);
        aoff[mi] = row * 256;
        asw[mi] = row & 7;
    }
    const uint32_t achb = lane >> 4;
    uint32_t boff[2], bsw[2];
#pragma unroll
    for (int g = 0; g < 2; ++g) {
        int row = warpN * 32 + g * 16 + (lane & 7) + ((lane >> 4) << 3);
        boff[g] = row * 256;
        bsw[g] = row & 7;
    }
    const uint32_t bchb = (lane >> 3) & 1;

    CP_WAIT(1);
    __syncthreads();                 // z + stage0 + sacc zero visible CTA-wide

    for (int i = 0; i < nch; ++i) {
        if (i > 0) {
            CP_WAIT(1);
            BAR_PAIR(pid);           // pair's stage (i&1) slice visible
        }

        const int cb = i & 1;
        const uint32_t bbase = sb + SM_B + cb * 32768;
        const uint32_t abase = sb + SM_ZH;

        uint32_t acch[4][4][2];
#pragma unroll
        for (int mi = 0; mi < 4; ++mi)
#pragma unroll
            for (int ni = 0; ni < 4; ++ni) { acch[mi][ni][0] = 0u; acch[mi][ni][1] = 0u; }

#pragma unroll
        for (int k8 = 0; k8 < 8; ++k8) {
            uint32_t af[4][4], bf[2][4];
            uint32_t ca = 2 * k8 + achb, cbk = 2 * k8 + bchb;
#pragma unroll
            for (int mi = 0; mi < 4; ++mi)
                LDSM4(af[mi], abase + aoff[mi] + ((ca ^ asw[mi]) << 4));
#pragma unroll
            for (int g = 0; g < 2; ++g)
                LDSM4(bf[g], bbase + boff[g] + ((cbk ^ bsw[g]) << 4));
#pragma unroll
            for (int mi = 0; mi < 4; ++mi)
#pragma unroll
                for (int ni = 0; ni < 4; ++ni) {
                    int g = ni >> 1, p = (ni & 1) * 2;
                    MMA_F16ACC(acch[mi][ni], af[mi], bf[g][p], bf[g][p + 1]);
                }
        }

        // pull candidate norms into registers BEFORE freeing the stage
        float cnv[4][2];
#pragma unroll
        for (int ni = 0; ni < 4; ++ni) {
            cnv[ni][0] = *(const float*)(sm + SM_CN + cb * 512 + (warpN * 32 + ni * 8 + q2) * 4);
            cnv[ni][1] = *(const float*)(sm + SM_CN + cb * 512 + (warpN * 32 + ni * 8 + q2 + 1) * 4);
        }

        BAR_PAIR(pid);               // pair's reads of its stage-cb slice done

        // prefetch chunk i+2 into pair's slice of stage cb; overlaps epilogue
        if (i + 2 < nch) {
            issue_pair_tile(sb + SM_B + cb * 32768,
                            (const uint4*)ch_g + (size_t)(cLo + i + 2) * 2048, pid, tid64);
            if (tid64 < 8) CP16(sb + SM_CN + cb * 512 + pid * 128 + tid64 * 16,
                                (const float*)cn_g + (size_t)(cLo + i + 2) * 128 +
                                pid * 32 + tid64 * 4);
        }
        CP_COMMIT();

        // unpack + dist -> exp(-dist)
        float acc[4][4][4];
#pragma unroll
        for (int mi = 0; mi < 4; ++mi)
#pragma unroll
            for (int ni = 0; ni < 4; ++ni) {
                float2 lo = u2f2(acch[mi][ni][0]);
                float2 hi = u2f2(acch[mi][ni][1]);
                acc[mi][ni][0] = lo.x; acc[mi][ni][1] = lo.y;
                acc[mi][ni][2] = hi.x; acc[mi][ni][3] = hi.y;
            }
#pragma unroll
        for (int ni = 0; ni < 4; ++ni)
#pragma unroll
            for (int mi = 0; mi < 4; ++mi)
#pragma unroll
                for (int k = 0; k < 4; ++k) {
                    float base = znr[mi][k >> 1] + cnv[ni][k & 1];
                    float sq = fmaf(-2.f, acc[mi][ni][k], base);
                    float dd;
                    asm("sqrt.approx.f32 %0, %1;" : "=f"(dd) : "f"(sq));
                    float nd = -dd;
                    asm("ex2.approx.f32 %0, %1;" : "=f"(acc[mi][ni][k]) : "f"(nd));
                }

        // class-segmented accumulation (candidates sorted by class)
        const int wb = (cLo + i) * 128 + warpN * 32;
        int c0 = 0;
        while (c0 < NCLS - 1 && cs[c0 + 1] <= wb) ++c0;
        int c1 = c0;
        while (c1 < NCLS - 1 && cs[c1 + 1] < wb + 32) ++c1;
        if (c0 == c1) {
#pragma unroll
            for (int mi = 0; mi < 4; ++mi)
#pragma unroll
                for (int h = 0; h < 2; ++h) {
                    float s = 0.f;
#pragma unroll
                    for (int ni = 0; ni < 4; ++ni)
#pragma unroll
                        for (int j = 0; j < 2; ++j) s += acc[mi][ni][h * 2 + j];
                    s += __shfl_xor_sync(FULLMASK, s, 1);
                    s += __shfl_xor_sync(FULLMASK, s, 2);
                    if ((lane & 3) == 0) {
                        int r = warpM * 64 + mi * 16 + (lane >> 2) + h * 8;
                        atomicAdd((float*)(sm + SM_SACC) + r * NCLS + c0, s);
                    }
                }
        } else {
            for (int c = c0; c <= c1; ++c) {
                int lo = max(cs[c] - wb, 0), hi = min(cs[c + 1] - wb, 32);
#pragma unroll
                for (int mi = 0; mi < 4; ++mi)
#pragma unroll
                    for (int h = 0; h < 2; ++h) {
                        float s = 0.f;
#pragma unroll
                        for (int ni = 0; ni < 4; ++ni)
#pragma unroll
                            for (int j = 0; j < 2; ++j) {
                                int nl = ni * 8 + q2 + j;
                                s += (nl >= lo && nl < hi) ? acc[mi][ni][h * 2 + j] : 0.f;
                            }
                        s += __shfl_xor_sync(FULLMASK, s, 1);
                        s += __shfl_xor_sync(FULLMASK, s, 2);
                        if ((lane & 3) == 0) {
                            int r = warpM * 64 + mi * 16 + (lane >> 2) + h * 8;
                            atomicAdd((float*)(sm + SM_SACC) + r * NCLS + c, s);
                        }
                    }
            }
        }
    }

    __syncthreads();                 // all pairs' atomicAdds complete
    if (tid < 128) {
        int qg = tile * 128 + tid;
#pragma unroll
        for (int c = 0; c < NCLS; ++c)
            part[((size_t)split * N + qg) * NCLS + c] =
                ((float*)(sm + SM_SACC))[tid * NCLS + c];
    }
}

// ---------------- finalize: combine splits, normalize, log ------------------
__global__ void finalize_k(const float* __restrict__ part, float* __restrict__ out, int N) {
    int n = blockIdx.x * blockDim.x + threadIdx.x;
    if (n >= N) return;
    float t[NCLS];
#pragma unroll
    for (int c = 0; c < NCLS; ++c) t[c] = 0.f;
    for (int s = 0; s < NSPLIT; ++s)
#pragma unroll
        for (int c = 0; c < NCLS; ++c) t[c] += part[((size_t)s * N + n) * NCLS + c];
    float tot = 0.f;
#pragma unroll
    for (int c = 0; c < NCLS; ++c) tot += t[c];
    float inv = 1.f / tot;
#pragma unroll
    for (int c = 0; c < NCLS; ++c) out[n * NCLS + c] = logf(fmaf(t[c], inv, 1e-7f));
}

// ---------------- launch ----------------------------------------------------
extern "C" void kernel_launch(void* const* d_in, const int* in_sizes, int n_in,
                              void* d_out, int out_size) {
    const float* x  = (const float*)d_in[0];
    const float* cx = (const float*)d_in[1];
    const int*   cy = (const int*)d_in[2];
    const float* W  = (const float*)d_in[3];
    const float* b  = (const float*)d_in[4];
    int N = in_sizes[0] / 128;
    int M = in_sizes[2];
    float* out = (float*)d_out;

    void *p_ch, *p_cn, *p_zh, *p_zn2, *p_wh, *p_dest, *p_hist, *p_cs, *p_part;
    cudaGetSymbolAddress(&p_ch, g_zc_h);
    cudaGetSymbolAddress(&p_cn, g_cn);
    cudaGetSymbolAddress(&p_zh, g_z_h);
    cudaGetSymbolAddress(&p_zn2, g_zn2);
    cudaGetSymbolAddress(&p_wh, g_Wh);
    cudaGetSymbolAddress(&p_dest, g_destMap);
    cudaGetSymbolAddress(&p_hist, g_hist);
    cudaGetSymbolAddress(&p_cs, g_classStart);
    cudaGetSymbolAddress(&p_part, g_part);

    int NB = (M + HB - 1) / HB;
    hist_k<<<NB + 16, HB>>>(cy, M, (int*)p_hist, NB, W, (__half*)p_wh);
    scan_k<<<1, 320>>>((int*)p_hist, NB, (int*)p_cs);
    scatter_k<<<NB, HB>>>(cy, M, (const int*)p_hist, (const int*)p_cs, (int*)p_dest);

    int nbQ = N / 64, nbC = M / 64;
    cudaFuncSetAttribute(encode_mma_k, cudaFuncAttributeMaxDynamicSharedMemorySize, E_TOTAL);
    encode_mma_k<<<nbQ + nbC, 256, E_TOTAL>>>(x, cx, nbQ, (const int*)p_dest,
        (const __half*)p_wh, b,
        (__half*)p_zh, (float*)p_zn2, (__half*)p_ch, (float*)p_cn);

    cudaFuncSetAttribute(nca_mma_k, cudaFuncAttributeMaxDynamicSharedMemorySize, SM_TOTAL);
    dim3 g(N / 128, NSPLIT);
    nca_mma_k<<<g, 256, SM_TOTAL>>>(
        (const __half*)p_zh, (const float*)p_zn2,
        (const __half*)p_ch, (const float*)p_cn,
        (const int*)p_cs, (float*)p_part, M, N);

    finalize_k<<<(N + 255) / 256, 256>>>((const float*)p_part, out, N);
}